// round 2
// baseline (speedup 1.0000x reference)
#include <cuda_runtime.h>

#define N_NODES 100000
#define N_EDGES 1600000
#define D 64
#define NGRAPH 256
#define EPS 1e-5f

// ---- scratch (static device globals; no allocation) ----
__device__ int   g_deg_out[N_NODES];
__device__ int   g_deg_in[N_NODES];
__device__ int   g_start[N_NODES];
__device__ int   g_cursor[N_NODES];
__device__ int   g_total;
__device__ int2  g_edge[N_EDGES];          // {src, weight-bits}
__device__ float g_h1[N_NODES * D];
__device__ float g_h2[N_NODES * D];

// ---------------------------------------------------------------- zero
__global__ void k_zero() {
    int i = blockIdx.x * blockDim.x + threadIdx.x;
    if (i < N_NODES) { g_deg_out[i] = 0; g_deg_in[i] = 0; }
    if (i == 0) g_total = 0;
}

// ---------------------------------------------------------------- degrees (4 edges/thread)
__global__ void k_degree(const int* __restrict__ src, const int* __restrict__ dst) {
    int e4 = blockIdx.x * blockDim.x + threadIdx.x;
    if (e4 * 4 >= N_EDGES) return;
    int4 s = ((const int4*)src)[e4];
    int4 d = ((const int4*)dst)[e4];
    atomicAdd(&g_deg_out[s.x], 1); atomicAdd(&g_deg_out[s.y], 1);
    atomicAdd(&g_deg_out[s.z], 1); atomicAdd(&g_deg_out[s.w], 1);
    atomicAdd(&g_deg_in[d.x], 1);  atomicAdd(&g_deg_in[d.y], 1);
    atomicAdd(&g_deg_in[d.z], 1);  atomicAdd(&g_deg_in[d.w], 1);
}

// ---------------------------------------------------------------- offsets: one-kernel scan
// block-local exclusive scan + atomic base from a global counter.
// (bucket start order is arbitrary across blocks; aggregation only needs
//  disjoint per-node ranges, which this provides.)
__global__ void k_offsets() {
    int i = blockIdx.x * 256 + threadIdx.x;
    int d = (i < N_NODES) ? g_deg_in[i] : 0;
    int lane = threadIdx.x & 31, wid = threadIdx.x >> 5;
    int s = d;
    #pragma unroll
    for (int o = 1; o < 32; o <<= 1) {
        int x = __shfl_up_sync(0xffffffffu, s, o);
        if (lane >= o) s += x;
    }
    __shared__ int woff[8];
    __shared__ int sbase;
    if (lane == 31) woff[wid] = s;
    __syncthreads();
    if (threadIdx.x < 8) {
        int w = woff[threadIdx.x];
        int t = w;
        #pragma unroll
        for (int o = 1; o < 8; o <<= 1) {
            int x = __shfl_up_sync(0xffu, t, o);
            if ((int)threadIdx.x >= o) t += x;
        }
        woff[threadIdx.x] = t - w;             // exclusive warp offset
        if (threadIdx.x == 7) sbase = atomicAdd(&g_total, t);
    }
    __syncthreads();
    if (i < N_NODES) {
        int start = sbase + woff[wid] + (s - d);
        g_start[i] = start;
        g_cursor[i] = start;
    }
}

// ---------------------------------------------------------------- bucket edges by dst
// folds source-side norm into weight: w_eff = ew * rsqrt(max(out_deg[src],1))
__global__ void k_bucket(const int* __restrict__ src, const int* __restrict__ dst,
                         const float* __restrict__ ew) {
    int e = blockIdx.x * blockDim.x + threadIdx.x;
    if (e >= N_EDGES) return;
    int s = src[e];
    int d = dst[e];
    float we = ew[e] * rsqrtf(fmaxf((float)g_deg_out[s], 1.f));
    int p = atomicAdd(&g_cursor[d], 1);
    g_edge[p] = make_int2(s, __float_as_int(we));
}

// ---------------------------------------------------------------- fused layer
// 128 nodes/block, 256 threads (8 warps x 16 rows).
// Aggregation: half-warps process 2 edges per iter (float4 per lane), unroll x2.
// GEMM: 8 nodes x 4 dims per thread, k chunked by 4 with float4 LDS.
#define ASH_STRIDE 68   // 17 float4s per row: conflict-safe
__global__ __launch_bounds__(256) void k_layer(
    const float* __restrict__ hin,
    const float* __restrict__ W,  const float* __restrict__ b,
    const float* __restrict__ gamma, const float* __restrict__ beta,
    const float* __restrict__ rm,    const float* __restrict__ rv,
    float* __restrict__ hout)
{
    extern __shared__ float sm[];
    float* Ash = sm;                      // 128 * 68 floats
    float* Wsh = sm + 128 * ASH_STRIDE;   // 64 * 64 floats

    int t = threadIdx.x;
    int lane = t & 31;
    int w = t >> 5;
    int q = lane & 15;      // dim-quad 0..15
    int p = lane >> 4;      // edge parity 0/1
    int nb = blockIdx.x * 128;

    // stage W [k][d]
    for (int j = t; j < 1024; j += 256)
        ((float4*)Wsh)[j] = ((const float4*)W)[j];

    const float4* hp4 = (const float4*)hin;

    #pragma unroll 1
    for (int i = 0; i < 16; i++) {
        int row = w * 16 + i;
        int n = nb + row;
        float4 acc = make_float4(0.f, 0.f, 0.f, 0.f);
        int deg = 0;
        if (n < N_NODES) {
            int e0 = g_start[n];
            deg = g_deg_in[n];
            int e1 = e0 + deg;
            int e = e0;
            for (; e + 4 <= e1; e += 4) {
                int2 r0 = g_edge[e + p];
                int2 r1 = g_edge[e + 2 + p];
                float4 v0 = hp4[(size_t)r0.x * 16 + q];
                float4 v1 = hp4[(size_t)r1.x * 16 + q];
                float w0 = __int_as_float(r0.y);
                float w1 = __int_as_float(r1.y);
                acc.x += v0.x * w0 + v1.x * w1;
                acc.y += v0.y * w0 + v1.y * w1;
                acc.z += v0.z * w0 + v1.z * w1;
                acc.w += v0.w * w0 + v1.w * w1;
            }
            for (; e < e1; e += 2) {
                int idx = e + p;
                bool ok = idx < e1;
                int2 r = g_edge[ok ? idx : e];
                float ww = ok ? __int_as_float(r.y) : 0.f;
                float4 v = hp4[(size_t)r.x * 16 + q];
                acc.x += v.x * ww; acc.y += v.y * ww;
                acc.z += v.z * ww; acc.w += v.w * ww;
            }
        }
        // combine the two half-warp partial sums
        acc.x += __shfl_xor_sync(0xffffffffu, acc.x, 16);
        acc.y += __shfl_xor_sync(0xffffffffu, acc.y, 16);
        acc.z += __shfl_xor_sync(0xffffffffu, acc.z, 16);
        acc.w += __shfl_xor_sync(0xffffffffu, acc.w, 16);
        float ri = rsqrtf(fmaxf((float)deg, 1.f));
        if (p == 0) {
            *(float4*)&Ash[row * ASH_STRIDE + q * 4] =
                make_float4(acc.x * ri, acc.y * ri, acc.z * ri, acc.w * ri);
        }
    }
    __syncthreads();

    // GEMM: thread tile 8 nodes x 4 dims
    int d0 = (t & 15) * 4;
    int n0 = (t >> 4) * 8;
    int dq = d0 >> 2;
    float4 acc[8];
    #pragma unroll
    for (int i = 0; i < 8; i++) acc[i] = make_float4(0.f, 0.f, 0.f, 0.f);

    const float4* A4 = (const float4*)Ash;
    const float4* W4 = (const float4*)Wsh;

    #pragma unroll
    for (int kq = 0; kq < 16; kq++) {
        float4 w0 = W4[(4 * kq + 0) * 16 + dq];
        float4 w1 = W4[(4 * kq + 1) * 16 + dq];
        float4 w2 = W4[(4 * kq + 2) * 16 + dq];
        float4 w3 = W4[(4 * kq + 3) * 16 + dq];
        #pragma unroll
        for (int i = 0; i < 8; i++) {
            float4 a = A4[(n0 + i) * (ASH_STRIDE / 4) + kq];
            acc[i].x += a.x * w0.x + a.y * w1.x + a.z * w2.x + a.w * w3.x;
            acc[i].y += a.x * w0.y + a.y * w1.y + a.z * w2.y + a.w * w3.y;
            acc[i].z += a.x * w0.z + a.y * w1.z + a.z * w2.z + a.w * w3.z;
            acc[i].w += a.x * w0.w + a.y * w1.w + a.z * w2.w + a.w * w3.w;
        }
    }

    // epilogue: +b, ReLU, BN(eval), ReLU
    float4 b4  = *(const float4*)&b[d0];
    float4 g4  = *(const float4*)&gamma[d0];
    float4 be4 = *(const float4*)&beta[d0];
    float4 rm4 = *(const float4*)&rm[d0];
    float4 rv4 = *(const float4*)&rv[d0];
    float s0 = rsqrtf(rv4.x + EPS) * g4.x;
    float s1 = rsqrtf(rv4.y + EPS) * g4.y;
    float s2 = rsqrtf(rv4.z + EPS) * g4.z;
    float s3 = rsqrtf(rv4.w + EPS) * g4.w;

    #pragma unroll
    for (int i = 0; i < 8; i++) {
        int n = nb + n0 + i;
        if (n >= N_NODES) continue;
        float4 o;
        o.x = fmaxf(acc[i].x + b4.x, 0.f);
        o.y = fmaxf(acc[i].y + b4.y, 0.f);
        o.z = fmaxf(acc[i].z + b4.z, 0.f);
        o.w = fmaxf(acc[i].w + b4.w, 0.f);
        o.x = fmaxf((o.x - rm4.x) * s0 + be4.x, 0.f);
        o.y = fmaxf((o.y - rm4.y) * s1 + be4.y, 0.f);
        o.z = fmaxf((o.z - rm4.z) * s2 + be4.z, 0.f);
        o.w = fmaxf((o.w - rm4.w) * s3 + be4.w, 0.f);
        ((float4*)hout)[n * 16 + dq] = o;
    }
}

// ---------------------------------------------------------------- readout
// node2graph sorted: block g binary-searches its node range, direct mean.
__global__ __launch_bounds__(256) void k_readout(const int* __restrict__ n2g,
                                                 float* __restrict__ out) {
    int g = blockIdx.x;
    __shared__ int slo, shi;
    if (threadIdx.x == 0) {
        int lo = 0, hi = N_NODES;
        while (lo < hi) { int m = (lo + hi) >> 1; if (n2g[m] < g) lo = m + 1; else hi = m; }
        slo = lo;
        hi = N_NODES;
        while (lo < hi) { int m = (lo + hi) >> 1; if (n2g[m] <= g) lo = m + 1; else hi = m; }
        shi = lo;
    }
    __syncthreads();
    int lo = slo, hi = shi;
    int d = threadIdx.x & 63;
    int rg = threadIdx.x >> 6;   // 4 row groups
    float acc = 0.f;
    for (int r = lo + rg; r < hi; r += 4)
        acc += g_h2[r * 64 + d];
    __shared__ float red[4][64];
    red[rg][d] = acc;
    __syncthreads();
    if (rg == 0) {
        float s = red[0][d] + red[1][d] + red[2][d] + red[3][d];
        out[g * 64 + d] = s / fmaxf((float)(hi - lo), 1.f);
    }
}

// ---------------------------------------------------------------- launch
extern "C" void kernel_launch(void* const* d_in, const int* in_sizes, int n_in,
                              void* d_out, int out_size) {
    const float* h   = (const float*)d_in[0];
    const float* ew  = (const float*)d_in[1];
    const int*   src = (const int*)d_in[2];
    const int*   dst = (const int*)d_in[3];
    const int*   n2g = (const int*)d_in[4];
    const float* W1 = (const float*)d_in[5];
    const float* b1 = (const float*)d_in[6];
    const float* gamma1 = (const float*)d_in[7];
    const float* beta1  = (const float*)d_in[8];
    const float* rm1 = (const float*)d_in[9];
    const float* rv1 = (const float*)d_in[10];
    const float* W2 = (const float*)d_in[11];
    const float* b2 = (const float*)d_in[12];
    const float* gamma2 = (const float*)d_in[13];
    const float* beta2  = (const float*)d_in[14];
    const float* rm2 = (const float*)d_in[15];
    const float* rv2 = (const float*)d_in[16];
    float* out = (float*)d_out;

    float* h1; cudaGetSymbolAddress((void**)&h1, g_h1);
    float* h2; cudaGetSymbolAddress((void**)&h2, g_h2);

    const int SMEM = (128 * ASH_STRIDE + 64 * 64) * 4;   // 51200 B
    cudaFuncSetAttribute(k_layer, cudaFuncAttributeMaxDynamicSharedMemorySize, SMEM);

    const int TB = 256;
    int gN = (N_NODES + TB - 1) / TB;
    int gE = (N_EDGES + TB - 1) / TB;
    int gE4 = (N_EDGES / 4 + TB - 1) / TB;

    k_zero<<<gN, TB>>>();
    k_degree<<<gE4, TB>>>(src, dst);
    k_offsets<<<gN, TB>>>();
    k_bucket<<<gE, TB>>>(src, dst, ew);

    int gL = (N_NODES + 127) / 128;
    k_layer<<<gL, 256, SMEM>>>(h,  W1, b1, gamma1, beta1, rm1, rv1, h1);
    k_layer<<<gL, 256, SMEM>>>(h1, W2, b2, gamma2, beta2, rm2, rv2, h2);

    k_readout<<<NGRAPH, 256>>>(n2g, out);
}

// round 3
// speedup vs baseline: 1.1509x; 1.1509x over previous
#include <cuda_runtime.h>

#define N_NODES 100000
#define N_EDGES 1600000
#define D 64
#define NGRAPH 256
#define EPS 1e-5f

// ---- scratch (static device globals; no allocation) ----
__device__ int   g_deg_out[N_NODES];
__device__ int   g_deg_in[N_NODES];
__device__ int   g_start[N_NODES];
__device__ int   g_cursor[N_NODES];
__device__ int   g_total;
__device__ int2  g_edge[N_EDGES];          // {src, weight-bits}
__device__ float g_h1[N_NODES * D];
__device__ float g_h2[N_NODES * D];

// ---------------------------------------------------------------- zero
__global__ void k_zero() {
    int i = blockIdx.x * blockDim.x + threadIdx.x;
    if (i < N_NODES) { g_deg_out[i] = 0; g_deg_in[i] = 0; }
    if (i == 0) g_total = 0;
}

// ---------------------------------------------------------------- degrees (4 edges/thread)
__global__ void k_degree(const int* __restrict__ src, const int* __restrict__ dst) {
    int e4 = blockIdx.x * blockDim.x + threadIdx.x;
    if (e4 * 4 >= N_EDGES) return;
    int4 s = ((const int4*)src)[e4];
    int4 d = ((const int4*)dst)[e4];
    atomicAdd(&g_deg_out[s.x], 1); atomicAdd(&g_deg_out[s.y], 1);
    atomicAdd(&g_deg_out[s.z], 1); atomicAdd(&g_deg_out[s.w], 1);
    atomicAdd(&g_deg_in[d.x], 1);  atomicAdd(&g_deg_in[d.y], 1);
    atomicAdd(&g_deg_in[d.z], 1);  atomicAdd(&g_deg_in[d.w], 1);
}

// ---------------------------------------------------------------- offsets: one-kernel scan
// block-local exclusive scan + atomic base from a global counter (block order
// of bucket ranges is arbitrary; aggregation only needs disjoint ranges).
__global__ void k_offsets() {
    int i = blockIdx.x * 256 + threadIdx.x;
    int d = (i < N_NODES) ? g_deg_in[i] : 0;
    int lane = threadIdx.x & 31, wid = threadIdx.x >> 5;
    int s = d;
    #pragma unroll
    for (int o = 1; o < 32; o <<= 1) {
        int x = __shfl_up_sync(0xffffffffu, s, o);
        if (lane >= o) s += x;
    }
    __shared__ int woff[8];
    __shared__ int sbase;
    if (lane == 31) woff[wid] = s;
    __syncthreads();
    if (threadIdx.x < 8) {
        int w = woff[threadIdx.x];
        int t = w;
        #pragma unroll
        for (int o = 1; o < 8; o <<= 1) {
            int x = __shfl_up_sync(0xffu, t, o);
            if ((int)threadIdx.x >= o) t += x;
        }
        woff[threadIdx.x] = t - w;             // exclusive warp offset
        if (threadIdx.x == 7) sbase = atomicAdd(&g_total, t);
    }
    __syncthreads();
    if (i < N_NODES) {
        int start = sbase + woff[wid] + (s - d);
        g_start[i] = start;
        g_cursor[i] = start;
    }
}

// ---------------------------------------------------------------- bucket edges by dst
// folds source-side norm into weight: w_eff = ew * rsqrt(max(out_deg[src],1))
__global__ void k_bucket(const int* __restrict__ src, const int* __restrict__ dst,
                         const float* __restrict__ ew) {
    int e = blockIdx.x * blockDim.x + threadIdx.x;
    if (e >= N_EDGES) return;
    int s = src[e];
    int d = dst[e];
    float we = ew[e] * rsqrtf(fmaxf((float)g_deg_out[s], 1.f));
    int p = atomicAdd(&g_cursor[d], 1);
    g_edge[p] = make_int2(s, __float_as_int(we));
}

// ---------------------------------------------------------------- fused layer
// 64 nodes/block, 256 threads, 8 warps x 8 nodes.
// Aggregation: full-warp float2 gathers, edge loop unrolled x4 (MLP=4).
// GEMM: 4 nodes x 4 dims per thread, k chunked by 4 with float4 LDS.
#define ASH_STRIDE 68   // floats per row: 272B, 16B-aligned, conflict-free
__global__ __launch_bounds__(256) void k_layer(
    const float* __restrict__ hin,
    const float* __restrict__ W,  const float* __restrict__ b,
    const float* __restrict__ gamma, const float* __restrict__ beta,
    const float* __restrict__ rm,    const float* __restrict__ rv,
    float* __restrict__ hout)
{
    __shared__ float Ash[64 * ASH_STRIDE];
    __shared__ float Wsh[64 * 64];

    int t = threadIdx.x;
    int lane = t & 31;
    int w = t >> 5;
    int nb = blockIdx.x * 64;

    // stage W [k][d]
    for (int j = t; j < 1024; j += 256)
        ((float4*)Wsh)[j] = ((const float4*)W)[j];

    const float2* hp = (const float2*)hin;

    #pragma unroll 1
    for (int i = 0; i < 8; i++) {
        int row = w * 8 + i;
        int n = nb + row;
        float2 a0 = make_float2(0.f, 0.f);
        float2 a1 = make_float2(0.f, 0.f);
        if (n < N_NODES) {
            int e0 = g_start[n];
            int deg = g_deg_in[n];
            int e1 = e0 + deg;
            int e = e0;
            for (; e + 4 <= e1; e += 4) {
                int2 r0 = g_edge[e + 0];
                int2 r1 = g_edge[e + 1];
                int2 r2 = g_edge[e + 2];
                int2 r3 = g_edge[e + 3];
                float2 v0 = hp[r0.x * 32 + lane];
                float2 v1 = hp[r1.x * 32 + lane];
                float2 v2 = hp[r2.x * 32 + lane];
                float2 v3 = hp[r3.x * 32 + lane];
                float w0 = __int_as_float(r0.y);
                float w1 = __int_as_float(r1.y);
                float w2 = __int_as_float(r2.y);
                float w3 = __int_as_float(r3.y);
                a0.x += v0.x * w0 + v2.x * w2;
                a0.y += v0.y * w0 + v2.y * w2;
                a1.x += v1.x * w1 + v3.x * w3;
                a1.y += v1.y * w1 + v3.y * w3;
            }
            for (; e < e1; e++) {
                int2 r = g_edge[e];
                float2 v = hp[r.x * 32 + lane];
                float ww = __int_as_float(r.y);
                a0.x += v.x * ww;
                a0.y += v.y * ww;
            }
            float ri = rsqrtf(fmaxf((float)deg, 1.f));
            a0.x = (a0.x + a1.x) * ri;
            a0.y = (a0.y + a1.y) * ri;
        }
        *(float2*)&Ash[row * ASH_STRIDE + 2 * lane] = a0;
    }
    __syncthreads();

    // GEMM: thread tile 4 nodes x 4 dims, k in chunks of 4 (float4 LDS)
    int d0 = (t & 15) * 4;
    int n0 = (t >> 4) * 4;
    int dq = d0 >> 2;
    float4 acc[4];
    #pragma unroll
    for (int i = 0; i < 4; i++) acc[i] = make_float4(0.f, 0.f, 0.f, 0.f);

    const float4* A4 = (const float4*)Ash;
    const float4* W4 = (const float4*)Wsh;

    #pragma unroll
    for (int kq = 0; kq < 16; kq++) {
        float4 w0 = W4[(4 * kq + 0) * 16 + dq];
        float4 w1 = W4[(4 * kq + 1) * 16 + dq];
        float4 w2 = W4[(4 * kq + 2) * 16 + dq];
        float4 w3 = W4[(4 * kq + 3) * 16 + dq];
        #pragma unroll
        for (int i = 0; i < 4; i++) {
            float4 a = A4[(n0 + i) * (ASH_STRIDE / 4) + kq];
            acc[i].x += a.x * w0.x + a.y * w1.x + a.z * w2.x + a.w * w3.x;
            acc[i].y += a.x * w0.y + a.y * w1.y + a.z * w2.y + a.w * w3.y;
            acc[i].z += a.x * w0.z + a.y * w1.z + a.z * w2.z + a.w * w3.z;
            acc[i].w += a.x * w0.w + a.y * w1.w + a.z * w2.w + a.w * w3.w;
        }
    }

    // epilogue: +b, ReLU, BN(eval), ReLU
    float4 b4  = *(const float4*)&b[d0];
    float4 g4  = *(const float4*)&gamma[d0];
    float4 be4 = *(const float4*)&beta[d0];
    float4 rm4 = *(const float4*)&rm[d0];
    float4 rv4 = *(const float4*)&rv[d0];
    float s0 = rsqrtf(rv4.x + EPS) * g4.x;
    float s1 = rsqrtf(rv4.y + EPS) * g4.y;
    float s2 = rsqrtf(rv4.z + EPS) * g4.z;
    float s3 = rsqrtf(rv4.w + EPS) * g4.w;

    #pragma unroll
    for (int i = 0; i < 4; i++) {
        int n = nb + n0 + i;
        if (n >= N_NODES) continue;
        float4 o;
        o.x = fmaxf(acc[i].x + b4.x, 0.f);
        o.y = fmaxf(acc[i].y + b4.y, 0.f);
        o.z = fmaxf(acc[i].z + b4.z, 0.f);
        o.w = fmaxf(acc[i].w + b4.w, 0.f);
        o.x = fmaxf((o.x - rm4.x) * s0 + be4.x, 0.f);
        o.y = fmaxf((o.y - rm4.y) * s1 + be4.y, 0.f);
        o.z = fmaxf((o.z - rm4.z) * s2 + be4.z, 0.f);
        o.w = fmaxf((o.w - rm4.w) * s3 + be4.w, 0.f);
        ((float4*)hout)[n * 16 + dq] = o;
    }
}

// ---------------------------------------------------------------- readout
// node2graph sorted: block g binary-searches its node range, direct mean.
__global__ __launch_bounds__(256) void k_readout(const int* __restrict__ n2g,
                                                 float* __restrict__ out) {
    int g = blockIdx.x;
    __shared__ int slo, shi;
    if (threadIdx.x == 0) {
        int lo = 0, hi = N_NODES;
        while (lo < hi) { int m = (lo + hi) >> 1; if (n2g[m] < g) lo = m + 1; else hi = m; }
        slo = lo;
        hi = N_NODES;
        while (lo < hi) { int m = (lo + hi) >> 1; if (n2g[m] <= g) lo = m + 1; else hi = m; }
        shi = lo;
    }
    __syncthreads();
    int lo = slo, hi = shi;
    int d = threadIdx.x & 63;
    int rg = threadIdx.x >> 6;   // 4 row groups
    float acc = 0.f;
    for (int r = lo + rg; r < hi; r += 4)
        acc += g_h2[r * 64 + d];
    __shared__ float red[4][64];
    red[rg][d] = acc;
    __syncthreads();
    if (rg == 0) {
        float s = red[0][d] + red[1][d] + red[2][d] + red[3][d];
        out[g * 64 + d] = s / fmaxf((float)(hi - lo), 1.f);
    }
}

// ---------------------------------------------------------------- launch
extern "C" void kernel_launch(void* const* d_in, const int* in_sizes, int n_in,
                              void* d_out, int out_size) {
    const float* h   = (const float*)d_in[0];
    const float* ew  = (const float*)d_in[1];
    const int*   src = (const int*)d_in[2];
    const int*   dst = (const int*)d_in[3];
    const int*   n2g = (const int*)d_in[4];
    const float* W1 = (const float*)d_in[5];
    const float* b1 = (const float*)d_in[6];
    const float* gamma1 = (const float*)d_in[7];
    const float* beta1  = (const float*)d_in[8];
    const float* rm1 = (const float*)d_in[9];
    const float* rv1 = (const float*)d_in[10];
    const float* W2 = (const float*)d_in[11];
    const float* b2 = (const float*)d_in[12];
    const float* gamma2 = (const float*)d_in[13];
    const float* beta2  = (const float*)d_in[14];
    const float* rm2 = (const float*)d_in[15];
    const float* rv2 = (const float*)d_in[16];
    float* out = (float*)d_out;

    float* h1; cudaGetSymbolAddress((void**)&h1, g_h1);
    float* h2; cudaGetSymbolAddress((void**)&h2, g_h2);

    const int TB = 256;
    int gN = (N_NODES + TB - 1) / TB;
    int gE = (N_EDGES + TB - 1) / TB;
    int gE4 = (N_EDGES / 4 + TB - 1) / TB;

    k_zero<<<gN, TB>>>();
    k_degree<<<gE4, TB>>>(src, dst);
    k_offsets<<<gN, TB>>>();
    k_bucket<<<gE, TB>>>(src, dst, ew);

    int gL = (N_NODES + 63) / 64;
    k_layer<<<gL, 256>>>(h,  W1, b1, gamma1, beta1, rm1, rv1, h1);
    k_layer<<<gL, 256>>>(h1, W2, b2, gamma2, beta2, rm2, rv2, h2);

    k_readout<<<NGRAPH, 256>>>(n2g, out);
}

// round 6
// speedup vs baseline: 1.1682x; 1.0150x over previous
#include <cuda_runtime.h>
#include <cuda_fp16.h>

#define N_NODES 100000
#define N_EDGES 1600000
#define D 64
#define NGRAPH 256
#define EPS 1e-5f

// fat-kernel block split for k_pre
#define GE4 ((N_EDGES / 4 + 255) / 256)          // 1563 degree blocks
#define GH  ((N_NODES * D / 8) / 256)            // 3125 convert blocks (exact)

// ---- scratch (static device globals; no allocation) ----
__device__ int    g_deg_out[N_NODES];
__device__ int    g_deg_in[N_NODES];
__device__ int    g_start[N_NODES];
__device__ int    g_cursor[N_NODES];
__device__ int    g_total;
__device__ int2   g_edge[N_EDGES];               // {src, fp32 weight bits}
__device__ __half g_hh0[N_NODES * D];            // fp16 input features
__device__ __half g_hh1[N_NODES * D];            // fp16 layer-1 output
__device__ float  g_h2[N_NODES * D];             // fp32 layer-2 output

// ---------------------------------------------------------------- zero
__global__ void k_zero() {
    int i = blockIdx.x * blockDim.x + threadIdx.x;
    if (i < N_NODES) { g_deg_out[i] = 0; g_deg_in[i] = 0; }
    if (i == 0) g_total = 0;
}

// ---------------------------------------------------------------- fat pre:
// blocks [0, GE4): degree histogram (4 edges/thread)
// blocks [GE4, GE4+GH): convert h -> fp16 (8 floats/thread)
__global__ void k_pre(const int* __restrict__ src, const int* __restrict__ dst,
                      const float* __restrict__ h) {
    int b = blockIdx.x;
    if (b < GE4) {
        int e4 = b * 256 + threadIdx.x;
        if (e4 * 4 >= N_EDGES) return;
        int4 s = ((const int4*)src)[e4];
        int4 d = ((const int4*)dst)[e4];
        atomicAdd(&g_deg_out[s.x], 1); atomicAdd(&g_deg_out[s.y], 1);
        atomicAdd(&g_deg_out[s.z], 1); atomicAdd(&g_deg_out[s.w], 1);
        atomicAdd(&g_deg_in[d.x], 1);  atomicAdd(&g_deg_in[d.y], 1);
        atomicAdd(&g_deg_in[d.z], 1);  atomicAdd(&g_deg_in[d.w], 1);
    } else {
        int i = (b - GE4) * 256 + threadIdx.x;   // group of 8 floats
        float4 a = ((const float4*)h)[i * 2];
        float4 c = ((const float4*)h)[i * 2 + 1];
        union { __half2 h2[4]; uint4 u; } pk;
        pk.h2[0] = __floats2half2_rn(a.x, a.y);
        pk.h2[1] = __floats2half2_rn(a.z, a.w);
        pk.h2[2] = __floats2half2_rn(c.x, c.y);
        pk.h2[3] = __floats2half2_rn(c.z, c.w);
        ((uint4*)g_hh0)[i] = pk.u;
    }
}

// ---------------------------------------------------------------- offsets: one-kernel scan
__global__ void k_offsets() {
    int i = blockIdx.x * 256 + threadIdx.x;
    int d = (i < N_NODES) ? g_deg_in[i] : 0;
    int lane = threadIdx.x & 31, wid = threadIdx.x >> 5;
    int s = d;
    #pragma unroll
    for (int o = 1; o < 32; o <<= 1) {
        int x = __shfl_up_sync(0xffffffffu, s, o);
        if (lane >= o) s += x;
    }
    __shared__ int woff[8];
    __shared__ int sbase;
    if (lane == 31) woff[wid] = s;
    __syncthreads();
    if (threadIdx.x < 8) {
        int w = woff[threadIdx.x];
        int t = w;
        #pragma unroll
        for (int o = 1; o < 8; o <<= 1) {
            int x = __shfl_up_sync(0xffu, t, o);
            if ((int)threadIdx.x >= o) t += x;
        }
        woff[threadIdx.x] = t - w;
        if (threadIdx.x == 7) sbase = atomicAdd(&g_total, t);
    }
    __syncthreads();
    if (i < N_NODES) {
        int start = sbase + woff[wid] + (s - d);
        g_start[i] = start;
        g_cursor[i] = start;
    }
}

// ---------------------------------------------------------------- bucket (2 edges/thread)
__global__ void k_bucket(const int* __restrict__ src, const int* __restrict__ dst,
                         const float* __restrict__ ew) {
    int e2 = (blockIdx.x * blockDim.x + threadIdx.x) * 2;
    if (e2 >= N_EDGES) return;
    int2 s = *(const int2*)(src + e2);
    int2 d = *(const int2*)(dst + e2);
    float2 w = *(const float2*)(ew + e2);
    float w0 = w.x * rsqrtf(fmaxf((float)g_deg_out[s.x], 1.f));
    float w1 = w.y * rsqrtf(fmaxf((float)g_deg_out[s.y], 1.f));
    int p0 = atomicAdd(&g_cursor[d.x], 1);
    int p1 = atomicAdd(&g_cursor[d.y], 1);
    g_edge[p0] = make_int2(s.x, __float_as_int(w0));
    g_edge[p1] = make_int2(s.y, __float_as_int(w1));
}

// ---------------------------------------------------------------- fused layer (fp16 gather)
// 64 nodes/block, 256 threads, 8 warps x 8 nodes.
// gather: half2 per lane (128B/edge), edge loop unrolled x4.
// GEMM fp32: 4 nodes x 4 dims per thread, k chunked by 4 with float4 LDS.
#define ASH_STRIDE 68
template <bool OUT_HALF>
__global__ __launch_bounds__(256) void k_layer(
    const __half* __restrict__ hin,
    const float* __restrict__ W,  const float* __restrict__ b,
    const float* __restrict__ gamma, const float* __restrict__ beta,
    const float* __restrict__ rm,    const float* __restrict__ rv,
    void* __restrict__ hout)
{
    __shared__ float Ash[64 * ASH_STRIDE];
    __shared__ float Wsh[64 * 64];

    int t = threadIdx.x;
    int lane = t & 31;
    int w = t >> 5;
    int nb = blockIdx.x * 64;

    for (int j = t; j < 1024; j += 256)
        ((float4*)Wsh)[j] = ((const float4*)W)[j];

    const __half2* hp = (const __half2*)hin;   // node row = 32 half2

    #pragma unroll 1
    for (int i = 0; i < 8; i++) {
        int row = w * 8 + i;
        int n = nb + row;
        float2 a0 = make_float2(0.f, 0.f);
        float2 a1 = make_float2(0.f, 0.f);
        if (n < N_NODES) {
            int e0 = g_start[n];
            int deg = g_deg_in[n];
            int e1 = e0 + deg;
            int e = e0;
            for (; e + 4 <= e1; e += 4) {
                int2 r0 = g_edge[e + 0];
                int2 r1 = g_edge[e + 1];
                int2 r2 = g_edge[e + 2];
                int2 r3 = g_edge[e + 3];
                float2 v0 = __half22float2(hp[r0.x * 32 + lane]);
                float2 v1 = __half22float2(hp[r1.x * 32 + lane]);
                float2 v2 = __half22float2(hp[r2.x * 32 + lane]);
                float2 v3 = __half22float2(hp[r3.x * 32 + lane]);
                float w0 = __int_as_float(r0.y);
                float w1 = __int_as_float(r1.y);
                float w2 = __int_as_float(r2.y);
                float w3 = __int_as_float(r3.y);
                a0.x += v0.x * w0 + v2.x * w2;
                a0.y += v0.y * w0 + v2.y * w2;
                a1.x += v1.x * w1 + v3.x * w3;
                a1.y += v1.y * w1 + v3.y * w3;
            }
            for (; e < e1; e++) {
                int2 r = g_edge[e];
                float2 v = __half22float2(hp[r.x * 32 + lane]);
                float ww = __int_as_float(r.y);
                a0.x += v.x * ww;
                a0.y += v.y * ww;
            }
            float ri = rsqrtf(fmaxf((float)deg, 1.f));
            a0.x = (a0.x + a1.x) * ri;
            a0.y = (a0.y + a1.y) * ri;
        }
        *(float2*)&Ash[row * ASH_STRIDE + 2 * lane] = a0;
    }
    __syncthreads();

    int d0 = (t & 15) * 4;
    int n0 = (t >> 4) * 4;
    int dq = d0 >> 2;
    float4 acc[4];
    #pragma unroll
    for (int i = 0; i < 4; i++) acc[i] = make_float4(0.f, 0.f, 0.f, 0.f);

    const float4* A4 = (const float4*)Ash;
    const float4* W4 = (const float4*)Wsh;

    #pragma unroll
    for (int kq = 0; kq < 16; kq++) {
        float4 w0 = W4[(4 * kq + 0) * 16 + dq];
        float4 w1 = W4[(4 * kq + 1) * 16 + dq];
        float4 w2 = W4[(4 * kq + 2) * 16 + dq];
        float4 w3 = W4[(4 * kq + 3) * 16 + dq];
        #pragma unroll
        for (int i = 0; i < 4; i++) {
            float4 a = A4[(n0 + i) * (ASH_STRIDE / 4) + kq];
            acc[i].x += a.x * w0.x + a.y * w1.x + a.z * w2.x + a.w * w3.x;
            acc[i].y += a.x * w0.y + a.y * w1.y + a.z * w2.y + a.w * w3.y;
            acc[i].z += a.x * w0.z + a.y * w1.z + a.z * w2.z + a.w * w3.z;
            acc[i].w += a.x * w0.w + a.y * w1.w + a.z * w2.w + a.w * w3.w;
        }
    }

    float4 b4  = *(const float4*)&b[d0];
    float4 g4  = *(const float4*)&gamma[d0];
    float4 be4 = *(const float4*)&beta[d0];
    float4 rm4 = *(const float4*)&rm[d0];
    float4 rv4 = *(const float4*)&rv[d0];
    float s0 = rsqrtf(rv4.x + EPS) * g4.x;
    float s1 = rsqrtf(rv4.y + EPS) * g4.y;
    float s2 = rsqrtf(rv4.z + EPS) * g4.z;
    float s3 = rsqrtf(rv4.w + EPS) * g4.w;

    #pragma unroll
    for (int i = 0; i < 4; i++) {
        int n = nb + n0 + i;
        if (n >= N_NODES) continue;
        float4 o;
        o.x = fmaxf(acc[i].x + b4.x, 0.f);
        o.y = fmaxf(acc[i].y + b4.y, 0.f);
        o.z = fmaxf(acc[i].z + b4.z, 0.f);
        o.w = fmaxf(acc[i].w + b4.w, 0.f);
        o.x = fmaxf((o.x - rm4.x) * s0 + be4.x, 0.f);
        o.y = fmaxf((o.y - rm4.y) * s1 + be4.y, 0.f);
        o.z = fmaxf((o.z - rm4.z) * s2 + be4.z, 0.f);
        o.w = fmaxf((o.w - rm4.w) * s3 + be4.w, 0.f);
        if (OUT_HALF) {
            union { __half2 h2[2]; uint2 u; } pk;
            pk.h2[0] = __floats2half2_rn(o.x, o.y);
            pk.h2[1] = __floats2half2_rn(o.z, o.w);
            ((uint2*)hout)[n * 16 + dq] = pk.u;
        } else {
            ((float4*)hout)[n * 16 + dq] = o;
        }
    }
}

// ---------------------------------------------------------------- readout
__global__ __launch_bounds__(256) void k_readout(const int* __restrict__ n2g,
                                                 float* __restrict__ out) {
    int g = blockIdx.x;
    __shared__ int slo, shi;
    if (threadIdx.x == 0) {
        int lo = 0, hi = N_NODES;
        while (lo < hi) { int m = (lo + hi) >> 1; if (n2g[m] < g) lo = m + 1; else hi = m; }
        slo = lo;
        hi = N_NODES;
        while (lo < hi) { int m = (lo + hi) >> 1; if (n2g[m] <= g) lo = m + 1; else hi = m; }
        shi = lo;
    }
    __syncthreads();
    int lo = slo, hi = shi;
    int d = threadIdx.x & 63;
    int rg = threadIdx.x >> 6;
    float acc = 0.f;
    for (int r = lo + rg; r < hi; r += 4)
        acc += g_h2[r * 64 + d];
    __shared__ float red[4][64];
    red[rg][d] = acc;
    __syncthreads();
    if (rg == 0) {
        float s = red[0][d] + red[1][d] + red[2][d] + red[3][d];
        out[g * 64 + d] = s / fmaxf((float)(hi - lo), 1.f);
    }
}

// ---------------------------------------------------------------- launch
extern "C" void kernel_launch(void* const* d_in, const int* in_sizes, int n_in,
                              void* d_out, int out_size) {
    const float* h   = (const float*)d_in[0];
    const float* ew  = (const float*)d_in[1];
    const int*   src = (const int*)d_in[2];
    const int*   dst = (const int*)d_in[3];
    const int*   n2g = (const int*)d_in[4];
    const float* W1 = (const float*)d_in[5];
    const float* b1 = (const float*)d_in[6];
    const float* gamma1 = (const float*)d_in[7];
    const float* beta1  = (const float*)d_in[8];
    const float* rm1 = (const float*)d_in[9];
    const float* rv1 = (const float*)d_in[10];
    const float* W2 = (const float*)d_in[11];
    const float* b2 = (const float*)d_in[12];
    const float* gamma2 = (const float*)d_in[13];
    const float* beta2  = (const float*)d_in[14];
    const float* rm2 = (const float*)d_in[15];
    const float* rv2 = (const float*)d_in[16];
    float* out = (float*)d_out;

    __half* hh0; cudaGetSymbolAddress((void**)&hh0, g_hh0);
    __half* hh1; cudaGetSymbolAddress((void**)&hh1, g_hh1);
    float*  h2;  cudaGetSymbolAddress((void**)&h2,  g_h2);

    const int TB = 256;
    int gN = (N_NODES + TB - 1) / TB;
    int gE2 = (N_EDGES / 2 + TB - 1) / TB;

    k_zero<<<gN, TB>>>();
    k_pre<<<GE4 + GH, TB>>>(src, dst, h);
    k_offsets<<<gN, TB>>>();
    k_bucket<<<gE2, TB>>>(src, dst, ew);

    int gL = (N_NODES + 63) / 64;
    k_layer<true ><<<gL, 256>>>(hh0, W1, b1, gamma1, beta1, rm1, rv1, hh1);
    k_layer<false><<<gL, 256>>>(hh1, W2, b2, gamma2, beta2, rm2, rv2, h2);

    k_readout<<<NGRAPH, 256>>>(n2g, out);
}

// round 7
// speedup vs baseline: 1.3415x; 1.1484x over previous
#include <cuda_runtime.h>
#include <cuda_fp16.h>

#define N_NODES 100000
#define N_EDGES 1600000
#define D 64
#define NGRAPH 256
#define EPS 1e-5f

// fat-kernel block split for k_pre
#define GE4 ((N_EDGES / 4 + 255) / 256)          // degree blocks
#define GH  ((N_NODES * D / 8) / 256)            // convert blocks (exact)

// ---- scratch (static device globals; no allocation) ----
__device__ int    g_deg_out[N_NODES];
__device__ int    g_deg_in[N_NODES];
__device__ int    g_start[N_NODES];
__device__ int    g_cursor[N_NODES];
__device__ int    g_total;
__device__ int2   g_edge[N_EDGES];               // {src, fp32 weight bits}
__device__ __half g_hh0[N_NODES * D];            // fp16 input features
__device__ __half g_hh1[N_NODES * D];            // fp16 layer-1 output
__device__ float  g_h2[N_NODES * D];             // fp32 layer-2 output

// ---------------------------------------------------------------- zero
__global__ void k_zero() {
    int i = blockIdx.x * blockDim.x + threadIdx.x;
    if (i < N_NODES) { g_deg_out[i] = 0; g_deg_in[i] = 0; }
    if (i == 0) g_total = 0;
}

// ---------------------------------------------------------------- fat pre
__global__ void k_pre(const int* __restrict__ src, const int* __restrict__ dst,
                      const float* __restrict__ h) {
    int b = blockIdx.x;
    if (b < GE4) {
        int e4 = b * 256 + threadIdx.x;
        if (e4 * 4 >= N_EDGES) return;
        int4 s = ((const int4*)src)[e4];
        int4 d = ((const int4*)dst)[e4];
        atomicAdd(&g_deg_out[s.x], 1); atomicAdd(&g_deg_out[s.y], 1);
        atomicAdd(&g_deg_out[s.z], 1); atomicAdd(&g_deg_out[s.w], 1);
        atomicAdd(&g_deg_in[d.x], 1);  atomicAdd(&g_deg_in[d.y], 1);
        atomicAdd(&g_deg_in[d.z], 1);  atomicAdd(&g_deg_in[d.w], 1);
    } else {
        int i = (b - GE4) * 256 + threadIdx.x;
        float4 a = ((const float4*)h)[i * 2];
        float4 c = ((const float4*)h)[i * 2 + 1];
        union { __half2 h2[4]; uint4 u; } pk;
        pk.h2[0] = __floats2half2_rn(a.x, a.y);
        pk.h2[1] = __floats2half2_rn(a.z, a.w);
        pk.h2[2] = __floats2half2_rn(c.x, c.y);
        pk.h2[3] = __floats2half2_rn(c.z, c.w);
        ((uint4*)g_hh0)[i] = pk.u;
    }
}

// ---------------------------------------------------------------- offsets: one-kernel scan
__global__ void k_offsets() {
    int i = blockIdx.x * 256 + threadIdx.x;
    int d = (i < N_NODES) ? g_deg_in[i] : 0;
    int lane = threadIdx.x & 31, wid = threadIdx.x >> 5;
    int s = d;
    #pragma unroll
    for (int o = 1; o < 32; o <<= 1) {
        int x = __shfl_up_sync(0xffffffffu, s, o);
        if (lane >= o) s += x;
    }
    __shared__ int woff[8];
    __shared__ int sbase;
    if (lane == 31) woff[wid] = s;
    __syncthreads();
    if (threadIdx.x < 8) {
        int w = woff[threadIdx.x];
        int t = w;
        #pragma unroll
        for (int o = 1; o < 8; o <<= 1) {
            int x = __shfl_up_sync(0xffu, t, o);
            if ((int)threadIdx.x >= o) t += x;
        }
        woff[threadIdx.x] = t - w;
        if (threadIdx.x == 7) sbase = atomicAdd(&g_total, t);
    }
    __syncthreads();
    if (i < N_NODES) {
        int start = sbase + woff[wid] + (s - d);
        g_start[i] = start;
        g_cursor[i] = start;
    }
}

// ---------------------------------------------------------------- bucket (2 edges/thread)
__global__ void k_bucket(const int* __restrict__ src, const int* __restrict__ dst,
                         const float* __restrict__ ew) {
    int e2 = (blockIdx.x * blockDim.x + threadIdx.x) * 2;
    if (e2 >= N_EDGES) return;
    int2 s = *(const int2*)(src + e2);
    int2 d = *(const int2*)(dst + e2);
    float2 w = *(const float2*)(ew + e2);
    float w0 = w.x * rsqrtf(fmaxf((float)g_deg_out[s.x], 1.f));
    float w1 = w.y * rsqrtf(fmaxf((float)g_deg_out[s.y], 1.f));
    int p0 = atomicAdd(&g_cursor[d.x], 1);
    int p1 = atomicAdd(&g_cursor[d.y], 1);
    g_edge[p0] = make_int2(s.x, __float_as_int(w0));
    g_edge[p1] = make_int2(s.y, __float_as_int(w1));
}

// ---------------------------------------------------------------- fused layer
// 64 nodes/block, 256 threads, 8 warps x 8 nodes.
// Aggregation: edge records staged coalesced via SMEM; gathers are LDG.128
// covering 4 edges/instruction (lane = 4 edge-groups x 8 dim-octets).
// Cross-group reduce via shfl_xor. GEMM fp32 from SMEM.
#define ASH_STRIDE 68
template <bool OUT_HALF>
__global__ __launch_bounds__(256) void k_layer(
    const __half* __restrict__ hin,
    const float* __restrict__ W,  const float* __restrict__ b,
    const float* __restrict__ gamma, const float* __restrict__ beta,
    const float* __restrict__ rm,    const float* __restrict__ rv,
    void* __restrict__ hout)
{
    __shared__ float Ash[64 * ASH_STRIDE];
    __shared__ float Wsh[64 * 64];
    __shared__ int2  ebuf[8][32];

    int t = threadIdx.x;
    int lane = t & 31;
    int w = t >> 5;
    int g = lane >> 3;      // edge subgroup 0..3
    int c = lane & 7;       // dim octet 0..7
    int nb = blockIdx.x * 64;

    for (int j = t; j < 1024; j += 256)
        ((float4*)Wsh)[j] = ((const float4*)W)[j];

    const uint4* hp4 = (const uint4*)hin;   // node row = 8 uint4 (128B)

    #pragma unroll 1
    for (int i = 0; i < 8; i++) {
        int row = w * 8 + i;
        int n = nb + row;
        float2 a0 = make_float2(0.f, 0.f);
        float2 a1 = make_float2(0.f, 0.f);
        float2 a2 = make_float2(0.f, 0.f);
        float2 a3 = make_float2(0.f, 0.f);
        int deg = 0;
        if (n < N_NODES) {
            int e0 = g_start[n];
            deg = g_deg_in[n];
            int e1 = e0 + deg;
            for (int e = e0; e < e1; e += 32) {
                int cnt = min(32, e1 - e);
                if (lane < cnt) ebuf[w][lane] = g_edge[e + lane];
                __syncwarp();
                int j = 0;
                // 8 edges (2 independent LDG.128) per iteration
                for (; j + 8 <= cnt; j += 8) {
                    int2 ra = ebuf[w][j + g];
                    int2 rb = ebuf[w][j + 4 + g];
                    uint4 va = hp4[ra.x * 8 + c];
                    uint4 vb = hp4[rb.x * 8 + c];
                    float wa = __int_as_float(ra.y);
                    float wb = __int_as_float(rb.y);
                    const __half2* ha = (const __half2*)&va;
                    const __half2* hb = (const __half2*)&vb;
                    float2 f;
                    f = __half22float2(ha[0]); a0.x += f.x * wa; a0.y += f.y * wa;
                    f = __half22float2(ha[1]); a1.x += f.x * wa; a1.y += f.y * wa;
                    f = __half22float2(ha[2]); a2.x += f.x * wa; a2.y += f.y * wa;
                    f = __half22float2(ha[3]); a3.x += f.x * wa; a3.y += f.y * wa;
                    f = __half22float2(hb[0]); a0.x += f.x * wb; a0.y += f.y * wb;
                    f = __half22float2(hb[1]); a1.x += f.x * wb; a1.y += f.y * wb;
                    f = __half22float2(hb[2]); a2.x += f.x * wb; a2.y += f.y * wb;
                    f = __half22float2(hb[3]); a3.x += f.x * wb; a3.y += f.y * wb;
                }
                if (j + 4 <= cnt) {
                    int2 r = ebuf[w][j + g];
                    uint4 v = hp4[r.x * 8 + c];
                    float ww = __int_as_float(r.y);
                    const __half2* hv = (const __half2*)&v;
                    float2 f;
                    f = __half22float2(hv[0]); a0.x += f.x * ww; a0.y += f.y * ww;
                    f = __half22float2(hv[1]); a1.x += f.x * ww; a1.y += f.y * ww;
                    f = __half22float2(hv[2]); a2.x += f.x * ww; a2.y += f.y * ww;
                    f = __half22float2(hv[3]); a3.x += f.x * ww; a3.y += f.y * ww;
                    j += 4;
                }
                int rem = cnt - j;
                if (g < rem) {
                    int2 r = ebuf[w][j + g];
                    uint4 v = hp4[r.x * 8 + c];
                    float ww = __int_as_float(r.y);
                    const __half2* hv = (const __half2*)&v;
                    float2 f;
                    f = __half22float2(hv[0]); a0.x += f.x * ww; a0.y += f.y * ww;
                    f = __half22float2(hv[1]); a1.x += f.x * ww; a1.y += f.y * ww;
                    f = __half22float2(hv[2]); a2.x += f.x * ww; a2.y += f.y * ww;
                    f = __half22float2(hv[3]); a3.x += f.x * ww; a3.y += f.y * ww;
                }
                __syncwarp();
            }
        }
        // reduce across the 4 edge subgroups (xor 8, then 16)
        #pragma unroll
        for (int m = 8; m <= 16; m <<= 1) {
            a0.x += __shfl_xor_sync(0xffffffffu, a0.x, m);
            a0.y += __shfl_xor_sync(0xffffffffu, a0.y, m);
            a1.x += __shfl_xor_sync(0xffffffffu, a1.x, m);
            a1.y += __shfl_xor_sync(0xffffffffu, a1.y, m);
            a2.x += __shfl_xor_sync(0xffffffffu, a2.x, m);
            a2.y += __shfl_xor_sync(0xffffffffu, a2.y, m);
            a3.x += __shfl_xor_sync(0xffffffffu, a3.x, m);
            a3.y += __shfl_xor_sync(0xffffffffu, a3.y, m);
        }
        if (g == 0) {
            float ri = rsqrtf(fmaxf((float)deg, 1.f));
            float* ap = &Ash[row * ASH_STRIDE + c * 8];
            *(float4*)(ap + 0) = make_float4(a0.x * ri, a0.y * ri, a1.x * ri, a1.y * ri);
            *(float4*)(ap + 4) = make_float4(a2.x * ri, a2.y * ri, a3.x * ri, a3.y * ri);
        }
    }
    __syncthreads();

    // GEMM: thread tile 4 nodes x 4 dims, k in chunks of 4 (float4 LDS)
    int d0 = (t & 15) * 4;
    int n0 = (t >> 4) * 4;
    int dq = d0 >> 2;
    float4 acc[4];
    #pragma unroll
    for (int i = 0; i < 4; i++) acc[i] = make_float4(0.f, 0.f, 0.f, 0.f);

    const float4* A4 = (const float4*)Ash;
    const float4* W4 = (const float4*)Wsh;

    #pragma unroll
    for (int kq = 0; kq < 16; kq++) {
        float4 w0 = W4[(4 * kq + 0) * 16 + dq];
        float4 w1 = W4[(4 * kq + 1) * 16 + dq];
        float4 w2 = W4[(4 * kq + 2) * 16 + dq];
        float4 w3 = W4[(4 * kq + 3) * 16 + dq];
        #pragma unroll
        for (int i = 0; i < 4; i++) {
            float4 a = A4[(n0 + i) * (ASH_STRIDE / 4) + kq];
            acc[i].x += a.x * w0.x + a.y * w1.x + a.z * w2.x + a.w * w3.x;
            acc[i].y += a.x * w0.y + a.y * w1.y + a.z * w2.y + a.w * w3.y;
            acc[i].z += a.x * w0.z + a.y * w1.z + a.z * w2.z + a.w * w3.z;
            acc[i].w += a.x * w0.w + a.y * w1.w + a.z * w2.w + a.w * w3.w;
        }
    }

    float4 b4  = *(const float4*)&b[d0];
    float4 g4  = *(const float4*)&gamma[d0];
    float4 be4 = *(const float4*)&beta[d0];
    float4 rm4 = *(const float4*)&rm[d0];
    float4 rv4 = *(const float4*)&rv[d0];
    float s0 = rsqrtf(rv4.x + EPS) * g4.x;
    float s1 = rsqrtf(rv4.y + EPS) * g4.y;
    float s2 = rsqrtf(rv4.z + EPS) * g4.z;
    float s3 = rsqrtf(rv4.w + EPS) * g4.w;

    #pragma unroll
    for (int i = 0; i < 4; i++) {
        int n = nb + n0 + i;
        if (n >= N_NODES) continue;
        float4 o;
        o.x = fmaxf(acc[i].x + b4.x, 0.f);
        o.y = fmaxf(acc[i].y + b4.y, 0.f);
        o.z = fmaxf(acc[i].z + b4.z, 0.f);
        o.w = fmaxf(acc[i].w + b4.w, 0.f);
        o.x = fmaxf((o.x - rm4.x) * s0 + be4.x, 0.f);
        o.y = fmaxf((o.y - rm4.y) * s1 + be4.y, 0.f);
        o.z = fmaxf((o.z - rm4.z) * s2 + be4.z, 0.f);
        o.w = fmaxf((o.w - rm4.w) * s3 + be4.w, 0.f);
        if (OUT_HALF) {
            union { __half2 h2[2]; uint2 u; } pk;
            pk.h2[0] = __floats2half2_rn(o.x, o.y);
            pk.h2[1] = __floats2half2_rn(o.z, o.w);
            ((uint2*)hout)[n * 16 + dq] = pk.u;
        } else {
            ((float4*)hout)[n * 16 + dq] = o;
        }
    }
}

// ---------------------------------------------------------------- readout
__global__ __launch_bounds__(256) void k_readout(const int* __restrict__ n2g,
                                                 float* __restrict__ out) {
    int g = blockIdx.x;
    __shared__ int slo, shi;
    if (threadIdx.x == 0) {
        int lo = 0, hi = N_NODES;
        while (lo < hi) { int m = (lo + hi) >> 1; if (n2g[m] < g) lo = m + 1; else hi = m; }
        slo = lo;
        hi = N_NODES;
        while (lo < hi) { int m = (lo + hi) >> 1; if (n2g[m] <= g) lo = m + 1; else hi = m; }
        shi = lo;
    }
    __syncthreads();
    int lo = slo, hi = shi;
    int d = threadIdx.x & 63;
    int rg = threadIdx.x >> 6;
    float acc = 0.f;
    for (int r = lo + rg; r < hi; r += 4)
        acc += g_h2[r * 64 + d];
    __shared__ float red[4][64];
    red[rg][d] = acc;
    __syncthreads();
    if (rg == 0) {
        float s = red[0][d] + red[1][d] + red[2][d] + red[3][d];
        out[g * 64 + d] = s / fmaxf((float)(hi - lo), 1.f);
    }
}

// ---------------------------------------------------------------- launch
extern "C" void kernel_launch(void* const* d_in, const int* in_sizes, int n_in,
                              void* d_out, int out_size) {
    const float* h   = (const float*)d_in[0];
    const float* ew  = (const float*)d_in[1];
    const int*   src = (const int*)d_in[2];
    const int*   dst = (const int*)d_in[3];
    const int*   n2g = (const int*)d_in[4];
    const float* W1 = (const float*)d_in[5];
    const float* b1 = (const float*)d_in[6];
    const float* gamma1 = (const float*)d_in[7];
    const float* beta1  = (const float*)d_in[8];
    const float* rm1 = (const float*)d_in[9];
    const float* rv1 = (const float*)d_in[10];
    const float* W2 = (const float*)d_in[11];
    const float* b2 = (const float*)d_in[12];
    const float* gamma2 = (const float*)d_in[13];
    const float* beta2  = (const float*)d_in[14];
    const float* rm2 = (const float*)d_in[15];
    const float* rv2 = (const float*)d_in[16];
    float* out = (float*)d_out;

    __half* hh0; cudaGetSymbolAddress((void**)&hh0, g_hh0);
    __half* hh1; cudaGetSymbolAddress((void**)&hh1, g_hh1);
    float*  h2;  cudaGetSymbolAddress((void**)&h2,  g_h2);

    const int TB = 256;
    int gN = (N_NODES + TB - 1) / TB;
    int gE2 = (N_EDGES / 2 + TB - 1) / TB;

    k_zero<<<gN, TB>>>();
    k_pre<<<GE4 + GH, TB>>>(src, dst, h);
    k_offsets<<<gN, TB>>>();
    k_bucket<<<gE2, TB>>>(src, dst, ew);

    int gL = (N_NODES + 63) / 64;
    k_layer<true ><<<gL, 256>>>(hh0, W1, b1, gamma1, beta1, rm1, rv1, hh1);
    k_layer<false><<<gL, 256>>>(hh1, W2, b2, gamma2, beta2, rm2, rv2, h2);

    k_readout<<<NGRAPH, 256>>>(n2g, out);
}

// round 9
// speedup vs baseline: 1.5799x; 1.1777x over previous
#include <cuda_runtime.h>
#include <cuda_fp16.h>
#include <cstdint>

#define N_NODES 100000
#define N_EDGES 1600000
#define D 64
#define NGRAPH 256
#define EPS 1e-5f

#define GE4 ((N_EDGES / 4 + 255) / 256)
#define GH  ((N_NODES * D / 8) / 256)

// ---- scratch ----
__device__ int    g_deg_out[N_NODES];
__device__ int    g_deg_in[N_NODES];
__device__ int    g_start[N_NODES];
__device__ int    g_cursor[N_NODES];
__device__ int    g_total;
__device__ int2   g_edge[N_EDGES];
__device__ __half g_hh0[N_NODES * D];
__device__ __half g_hh1[N_NODES * D];
__device__ float  g_h2[N_NODES * D];

__device__ __forceinline__ uint32_t smem_u32(const void* p) {
    uint32_t a;
    asm("{ .reg .u64 t; cvta.to.shared.u64 t, %1; cvt.u32.u64 %0, t; }"
        : "=r"(a) : "l"(p));
    return a;
}

// ---------------------------------------------------------------- zero
__global__ void k_zero() {
    int i = blockIdx.x * blockDim.x + threadIdx.x;
    if (i < N_NODES) { g_deg_out[i] = 0; g_deg_in[i] = 0; }
    if (i == 0) g_total = 0;
}

// ---------------------------------------------------------------- fat pre
__global__ void k_pre(const int* __restrict__ src, const int* __restrict__ dst,
                      const float* __restrict__ h) {
    int b = blockIdx.x;
    if (b < GE4) {
        int e4 = b * 256 + threadIdx.x;
        if (e4 * 4 >= N_EDGES) return;
        int4 s = ((const int4*)src)[e4];
        int4 d = ((const int4*)dst)[e4];
        atomicAdd(&g_deg_out[s.x], 1); atomicAdd(&g_deg_out[s.y], 1);
        atomicAdd(&g_deg_out[s.z], 1); atomicAdd(&g_deg_out[s.w], 1);
        atomicAdd(&g_deg_in[d.x], 1);  atomicAdd(&g_deg_in[d.y], 1);
        atomicAdd(&g_deg_in[d.z], 1);  atomicAdd(&g_deg_in[d.w], 1);
    } else {
        int i = (b - GE4) * 256 + threadIdx.x;
        float4 a = ((const float4*)h)[i * 2];
        float4 c = ((const float4*)h)[i * 2 + 1];
        union { __half2 h2[4]; uint4 u; } pk;
        pk.h2[0] = __floats2half2_rn(a.x, a.y);
        pk.h2[1] = __floats2half2_rn(a.z, a.w);
        pk.h2[2] = __floats2half2_rn(c.x, c.y);
        pk.h2[3] = __floats2half2_rn(c.z, c.w);
        ((uint4*)g_hh0)[i] = pk.u;
    }
}

// ---------------------------------------------------------------- offsets
__global__ void k_offsets() {
    int i = blockIdx.x * 256 + threadIdx.x;
    int d = (i < N_NODES) ? g_deg_in[i] : 0;
    int lane = threadIdx.x & 31, wid = threadIdx.x >> 5;
    int s = d;
    #pragma unroll
    for (int o = 1; o < 32; o <<= 1) {
        int x = __shfl_up_sync(0xffffffffu, s, o);
        if (lane >= o) s += x;
    }
    __shared__ int woff[8];
    __shared__ int sbase;
    if (lane == 31) woff[wid] = s;
    __syncthreads();
    if (threadIdx.x < 8) {
        int w = woff[threadIdx.x];
        int t = w;
        #pragma unroll
        for (int o = 1; o < 8; o <<= 1) {
            int x = __shfl_up_sync(0xffu, t, o);
            if ((int)threadIdx.x >= o) t += x;
        }
        woff[threadIdx.x] = t - w;
        if (threadIdx.x == 7) sbase = atomicAdd(&g_total, t);
    }
    __syncthreads();
    if (i < N_NODES) {
        int start = sbase + woff[wid] + (s - d);
        g_start[i] = start;
        g_cursor[i] = start;
    }
}

// ---------------------------------------------------------------- bucket
__global__ void k_bucket(const int* __restrict__ src, const int* __restrict__ dst,
                         const float* __restrict__ ew) {
    int e2 = (blockIdx.x * blockDim.x + threadIdx.x) * 2;
    if (e2 >= N_EDGES) return;
    int2 s = *(const int2*)(src + e2);
    int2 d = *(const int2*)(dst + e2);
    float2 w = *(const float2*)(ew + e2);
    float w0 = w.x * rsqrtf(fmaxf((float)g_deg_out[s.x], 1.f));
    float w1 = w.y * rsqrtf(fmaxf((float)g_deg_out[s.y], 1.f));
    int p0 = atomicAdd(&g_cursor[d.x], 1);
    int p1 = atomicAdd(&g_cursor[d.y], 1);
    g_edge[p0] = make_int2(s.x, __float_as_int(w0));
    g_edge[p1] = make_int2(s.y, __float_as_int(w1));
}

// ---------------------------------------------------------------- agg inner: 8 edges/iter
__device__ __forceinline__ void agg_batch(const uint4* __restrict__ hp4, int2 rec,
                                          int cnt, int g, int c,
                                          float2& a0, float2& a1, float2& a2, float2& a3) {
    for (int j = 0; j < cnt; j += 8) {
        int sa  = __shfl_sync(0xffffffffu, rec.x, j + g);
        int wai = __shfl_sync(0xffffffffu, rec.y, j + g);
        int sb  = __shfl_sync(0xffffffffu, rec.x, j + 4 + g);
        int wbi = __shfl_sync(0xffffffffu, rec.y, j + 4 + g);
        uint4 va = hp4[(size_t)sa * 8 + c];
        uint4 vb = hp4[(size_t)sb * 8 + c];
        float wa = __int_as_float(wai);
        float wb = __int_as_float(wbi);
        const __half2* ha = (const __half2*)&va;
        const __half2* hb = (const __half2*)&vb;
        float2 f;
        f = __half22float2(ha[0]); a0.x += f.x * wa; a0.y += f.y * wa;
        f = __half22float2(ha[1]); a1.x += f.x * wa; a1.y += f.y * wa;
        f = __half22float2(ha[2]); a2.x += f.x * wa; a2.y += f.y * wa;
        f = __half22float2(ha[3]); a3.x += f.x * wa; a3.y += f.y * wa;
        f = __half22float2(hb[0]); a0.x += f.x * wb; a0.y += f.y * wb;
        f = __half22float2(hb[1]); a1.x += f.x * wb; a1.y += f.y * wb;
        f = __half22float2(hb[2]); a2.x += f.x * wb; a2.y += f.y * wb;
        f = __half22float2(hb[3]); a3.x += f.x * wb; a3.y += f.y * wb;
    }
}

// ---------------------------------------------------------------- fused layer
// 128 nodes/block, 256 threads, 8 warps. Warp w aggregates nodes [w*16, w*16+16)
// into fp16 Ash rows (stride 144B), then does its OWN m16n8k16 HMMA tile
// (M=16, N=64, K=64) with W staged fp16-transposed in SMEM. BN fused epilogue.
#define AST 72   // halves per Ash row (144 B)
template <bool OUT_HALF>
__global__ __launch_bounds__(256, 3) void k_layer(
    const __half* __restrict__ hin,
    const float* __restrict__ W,  const float* __restrict__ b,
    const float* __restrict__ gamma, const float* __restrict__ beta,
    const float* __restrict__ rm,    const float* __restrict__ rv,
    void* __restrict__ hout)
{
    __shared__ __half Ash[128 * AST];
    __shared__ __half Wt[64 * AST];
    __shared__ float s_scale[64], s_shift[64], s_bias[64];

    int t = threadIdx.x;
    int lane = t & 31;
    int w = t >> 5;
    int g = lane >> 3;
    int c = lane & 7;
    int nb = blockIdx.x * 128;

    // stage W fp32 [k][n] -> fp16 transposed Wt [n][k]
    for (int j4 = t; j4 < 1024; j4 += 256) {
        float4 v = ((const float4*)W)[j4];
        int lin = j4 * 4;
        int k = lin >> 6;
        int n = lin & 63;
        Wt[(n + 0) * AST + k] = __float2half(v.x);
        Wt[(n + 1) * AST + k] = __float2half(v.y);
        Wt[(n + 2) * AST + k] = __float2half(v.z);
        Wt[(n + 3) * AST + k] = __float2half(v.w);
    }
    if (t < 64) {
        float sc = rsqrtf(rv[t] + EPS) * gamma[t];
        s_scale[t] = sc;
        s_shift[t] = beta[t] - rm[t] * sc;
        s_bias[t]  = b[t];
    }
    __syncthreads();   // only block-wide barrier: Wt + BN constants visible

    // ---- aggregation: warp handles 16 nodes ----
    const uint4* hp4 = (const uint4*)hin;
    int nwbase = nb + w * 16;
    int ms = 0, md = 0;
    {
        int nn = nwbase + lane;
        if (lane < 16 && nn < N_NODES) { ms = g_start[nn]; md = g_deg_in[nn]; }
    }
    int e0n = __shfl_sync(0xffffffffu, ms, 0);
    int dgn = __shfl_sync(0xffffffffu, md, 0);
    int2 recn = make_int2(0, 0);
    if (lane < min(dgn, 32)) recn = g_edge[e0n + lane];

    #pragma unroll 1
    for (int i = 0; i < 16; i++) {
        int e0 = e0n, deg = dgn;
        int2 rec = recn;
        if (i < 15) {
            e0n = __shfl_sync(0xffffffffu, ms, i + 1);
            dgn = __shfl_sync(0xffffffffu, md, i + 1);
            recn = make_int2(0, 0);
            if (lane < min(dgn, 32)) recn = g_edge[e0n + lane];
        }
        float2 a0 = make_float2(0.f, 0.f), a1 = a0, a2 = a0, a3 = a0;
        agg_batch(hp4, rec, min(deg, 32), g, c, a0, a1, a2, a3);
        for (int e = e0 + 32; e < e0 + deg; e += 32) {
            int c2 = min(32, e0 + deg - e);
            int2 r2 = make_int2(0, 0);
            if (lane < c2) r2 = g_edge[e + lane];
            agg_batch(hp4, r2, c2, g, c, a0, a1, a2, a3);
        }
        #pragma unroll
        for (int m = 8; m <= 16; m <<= 1) {
            a0.x += __shfl_xor_sync(0xffffffffu, a0.x, m);
            a0.y += __shfl_xor_sync(0xffffffffu, a0.y, m);
            a1.x += __shfl_xor_sync(0xffffffffu, a1.x, m);
            a1.y += __shfl_xor_sync(0xffffffffu, a1.y, m);
            a2.x += __shfl_xor_sync(0xffffffffu, a2.x, m);
            a2.y += __shfl_xor_sync(0xffffffffu, a2.y, m);
            a3.x += __shfl_xor_sync(0xffffffffu, a3.x, m);
            a3.y += __shfl_xor_sync(0xffffffffu, a3.y, m);
        }
        if (g == 0) {
            float ri = rsqrtf(fmaxf((float)deg, 1.f));
            union { __half2 h2[4]; uint4 u; } pk;
            pk.h2[0] = __floats2half2_rn(a0.x * ri, a0.y * ri);
            pk.h2[1] = __floats2half2_rn(a1.x * ri, a1.y * ri);
            pk.h2[2] = __floats2half2_rn(a2.x * ri, a2.y * ri);
            pk.h2[3] = __floats2half2_rn(a3.x * ri, a3.y * ri);
            int row = w * 16 + i;
            *(uint4*)((char*)Ash + row * 144 + c * 16) = pk.u;
        }
    }
    __syncwarp();

    // ---- per-warp HMMA: M=16 (own rows) x N=64, K=64 ----
    float acc[8][4];
    #pragma unroll
    for (int nt = 0; nt < 8; nt++)
        #pragma unroll
        for (int j = 0; j < 4; j++) acc[nt][j] = 0.f;

    // ldmatrix lane addressing: rows (lane&15), k-halves (lane>>4)*8
    uint32_t a_base = smem_u32(Ash) + (w * 16 + (lane & 15)) * 144 + (lane >> 4) * 16;
    int bn = lane >> 2;          // B fragment n within tile
    int bks = (lane & 3) * 2;    // B fragment k pair

    #pragma unroll
    for (int ks = 0; ks < 4; ks++) {
        uint32_t a0, a1, a2, a3;
        asm volatile("ldmatrix.sync.aligned.m8n8.x4.shared.b16 {%0,%1,%2,%3}, [%4];"
            : "=r"(a0), "=r"(a1), "=r"(a2), "=r"(a3)
            : "r"(a_base + ks * 32));
        int kb = ks * 16;
        #pragma unroll
        for (int nt = 0; nt < 8; nt++) {
            uint32_t b0 = *(const uint32_t*)&Wt[(nt * 8 + bn) * AST + kb + bks];
            uint32_t b1 = *(const uint32_t*)&Wt[(nt * 8 + bn) * AST + kb + bks + 8];
            asm volatile(
                "mma.sync.aligned.m16n8k16.row.col.f32.f16.f16.f32 "
                "{%0,%1,%2,%3}, {%4,%5,%6,%7}, {%8,%9}, {%0,%1,%2,%3};"
                : "+f"(acc[nt][0]), "+f"(acc[nt][1]), "+f"(acc[nt][2]), "+f"(acc[nt][3])
                : "r"(a0), "r"(a1), "r"(a2), "r"(a3), "r"(b0), "r"(b1));
        }
    }

    // ---- epilogue: BN fused, direct stores ----
    int r0 = nb + w * 16 + (lane >> 2);
    int r1 = r0 + 8;
    #pragma unroll
    for (int nt = 0; nt < 8; nt++) {
        int col = nt * 8 + (lane & 3) * 2;
        float sc0 = s_scale[col],     sc1 = s_scale[col + 1];
        float sh0 = s_shift[col],     sh1 = s_shift[col + 1];
        float bb0 = s_bias[col],      bb1 = s_bias[col + 1];
        float y00 = fmaxf(fmaxf(acc[nt][0] + bb0, 0.f) * sc0 + sh0, 0.f);
        float y01 = fmaxf(fmaxf(acc[nt][1] + bb1, 0.f) * sc1 + sh1, 0.f);
        float y10 = fmaxf(fmaxf(acc[nt][2] + bb0, 0.f) * sc0 + sh0, 0.f);
        float y11 = fmaxf(fmaxf(acc[nt][3] + bb1, 0.f) * sc1 + sh1, 0.f);
        if (OUT_HALF) {
            __half* o = (__half*)hout;
            if (r0 < N_NODES) *(__half2*)&o[r0 * 64 + col] = __floats2half2_rn(y00, y01);
            if (r1 < N_NODES) *(__half2*)&o[r1 * 64 + col] = __floats2half2_rn(y10, y11);
        } else {
            float* o = (float*)hout;
            if (r0 < N_NODES) *(float2*)&o[r0 * 64 + col] = make_float2(y00, y01);
            if (r1 < N_NODES) *(float2*)&o[r1 * 64 + col] = make_float2(y10, y11);
        }
    }
}

// ---------------------------------------------------------------- readout
__global__ __launch_bounds__(256) void k_readout(const int* __restrict__ n2g,
                                                 float* __restrict__ out) {
    int g = blockIdx.x;
    __shared__ int slo, shi;
    if (threadIdx.x == 0) {
        int lo = 0, hi = N_NODES;
        while (lo < hi) { int m = (lo + hi) >> 1; if (n2g[m] < g) lo = m + 1; else hi = m; }
        slo = lo;
        hi = N_NODES;
        while (lo < hi) { int m = (lo + hi) >> 1; if (n2g[m] <= g) lo = m + 1; else hi = m; }
        shi = lo;
    }
    __syncthreads();
    int lo = slo, hi = shi;
    int d = threadIdx.x & 63;
    int rg = threadIdx.x >> 6;
    float acc = 0.f;
    for (int r = lo + rg; r < hi; r += 4)
        acc += g_h2[r * 64 + d];
    __shared__ float red[4][64];
    red[rg][d] = acc;
    __syncthreads();
    if (rg == 0) {
        float s = red[0][d] + red[1][d] + red[2][d] + red[3][d];
        out[g * 64 + d] = s / fmaxf((float)(hi - lo), 1.f);
    }
}

// ---------------------------------------------------------------- launch
extern "C" void kernel_launch(void* const* d_in, const int* in_sizes, int n_in,
                              void* d_out, int out_size) {
    const float* h   = (const float*)d_in[0];
    const float* ew  = (const float*)d_in[1];
    const int*   src = (const int*)d_in[2];
    const int*   dst = (const int*)d_in[3];
    const int*   n2g = (const int*)d_in[4];
    const float* W1 = (const float*)d_in[5];
    const float* b1 = (const float*)d_in[6];
    const float* gamma1 = (const float*)d_in[7];
    const float* beta1  = (const float*)d_in[8];
    const float* rm1 = (const float*)d_in[9];
    const float* rv1 = (const float*)d_in[10];
    const float* W2 = (const float*)d_in[11];
    const float* b2 = (const float*)d_in[12];
    const float* gamma2 = (const float*)d_in[13];
    const float* beta2  = (const float*)d_in[14];
    const float* rm2 = (const float*)d_in[15];
    const float* rv2 = (const float*)d_in[16];
    float* out = (float*)d_out;

    __half* hh0; cudaGetSymbolAddress((void**)&hh0, g_hh0);
    __half* hh1; cudaGetSymbolAddress((void**)&hh1, g_hh1);
    float*  h2;  cudaGetSymbolAddress((void**)&h2,  g_h2);

    const int TB = 256;
    int gN = (N_NODES + TB - 1) / TB;
    int gE2 = (N_EDGES / 2 + TB - 1) / TB;

    k_zero<<<gN, TB>>>();
    k_pre<<<GE4 + GH, TB>>>(src, dst, h);
    k_offsets<<<gN, TB>>>();
    k_bucket<<<gE2, TB>>>(src, dst, ew);

    int gL = (N_NODES + 127) / 128;
    k_layer<true ><<<gL, 256>>>(hh0, W1, b1, gamma1, beta1, rm1, rv1, hh1);
    k_layer<false><<<gL, 256>>>(hh1, W2, b2, gamma2, beta2, rm2, rv2, h2);

    k_readout<<<NGRAPH, 256>>>(n2g, out);
}

// round 10
// speedup vs baseline: 1.5829x; 1.0020x over previous
#include <cuda_runtime.h>
#include <cuda_fp16.h>
#include <cstdint>

#define N_NODES 100000
#define N_EDGES 1600000
#define D 64
#define NGRAPH 256
#define EPS 1e-5f

#define GE4 ((N_EDGES / 4 + 255) / 256)
#define GH  ((N_NODES * D / 8) / 256)

// ---- scratch ----
__device__ int    g_deg_out[N_NODES];
__device__ int    g_deg_in[N_NODES];
__device__ int    g_start[N_NODES];
__device__ int    g_cursor[N_NODES];
__device__ int    g_total;
__device__ int2   g_edge[N_EDGES];
__device__ __half g_hh0[N_NODES * D];
__device__ __half g_hh1[N_NODES * D];
__device__ float  g_h2[N_NODES * D];

__device__ __forceinline__ uint32_t smem_u32(const void* p) {
    uint32_t a;
    asm("{ .reg .u64 t; cvta.to.shared.u64 t, %1; cvt.u32.u64 %0, t; }"
        : "=r"(a) : "l"(p));
    return a;
}

// ---------------------------------------------------------------- zero
__global__ void k_zero() {
    int i = blockIdx.x * blockDim.x + threadIdx.x;
    if (i < N_NODES) { g_deg_out[i] = 0; g_deg_in[i] = 0; }
    if (i == 0) g_total = 0;
}

// ---------------------------------------------------------------- fat pre
__global__ void k_pre(const int* __restrict__ src, const int* __restrict__ dst,
                      const float* __restrict__ h) {
    int b = blockIdx.x;
    if (b < GE4) {
        int e4 = b * 256 + threadIdx.x;
        if (e4 * 4 >= N_EDGES) return;
        int4 s = ((const int4*)src)[e4];
        int4 d = ((const int4*)dst)[e4];
        atomicAdd(&g_deg_out[s.x], 1); atomicAdd(&g_deg_out[s.y], 1);
        atomicAdd(&g_deg_out[s.z], 1); atomicAdd(&g_deg_out[s.w], 1);
        atomicAdd(&g_deg_in[d.x], 1);  atomicAdd(&g_deg_in[d.y], 1);
        atomicAdd(&g_deg_in[d.z], 1);  atomicAdd(&g_deg_in[d.w], 1);
    } else {
        int i = (b - GE4) * 256 + threadIdx.x;
        float4 a = ((const float4*)h)[i * 2];
        float4 c = ((const float4*)h)[i * 2 + 1];
        union { __half2 h2[4]; uint4 u; } pk;
        pk.h2[0] = __floats2half2_rn(a.x, a.y);
        pk.h2[1] = __floats2half2_rn(a.z, a.w);
        pk.h2[2] = __floats2half2_rn(c.x, c.y);
        pk.h2[3] = __floats2half2_rn(c.z, c.w);
        ((uint4*)g_hh0)[i] = pk.u;
    }
}

// ---------------------------------------------------------------- offsets
__global__ void k_offsets() {
    int i = blockIdx.x * 256 + threadIdx.x;
    int d = (i < N_NODES) ? g_deg_in[i] : 0;
    int lane = threadIdx.x & 31, wid = threadIdx.x >> 5;
    int s = d;
    #pragma unroll
    for (int o = 1; o < 32; o <<= 1) {
        int x = __shfl_up_sync(0xffffffffu, s, o);
        if (lane >= o) s += x;
    }
    __shared__ int woff[8];
    __shared__ int sbase;
    if (lane == 31) woff[wid] = s;
    __syncthreads();
    if (threadIdx.x < 8) {
        int w = woff[threadIdx.x];
        int t = w;
        #pragma unroll
        for (int o = 1; o < 8; o <<= 1) {
            int x = __shfl_up_sync(0xffu, t, o);
            if ((int)threadIdx.x >= o) t += x;
        }
        woff[threadIdx.x] = t - w;
        if (threadIdx.x == 7) sbase = atomicAdd(&g_total, t);
    }
    __syncthreads();
    if (i < N_NODES) {
        int start = sbase + woff[wid] + (s - d);
        g_start[i] = start;
        g_cursor[i] = start;
    }
}

// ---------------------------------------------------------------- bucket
__global__ void k_bucket(const int* __restrict__ src, const int* __restrict__ dst,
                         const float* __restrict__ ew) {
    int e2 = (blockIdx.x * blockDim.x + threadIdx.x) * 2;
    if (e2 >= N_EDGES) return;
    int2 s = *(const int2*)(src + e2);
    int2 d = *(const int2*)(dst + e2);
    float2 w = *(const float2*)(ew + e2);
    float w0 = w.x * rsqrtf(fmaxf((float)g_deg_out[s.x], 1.f));
    float w1 = w.y * rsqrtf(fmaxf((float)g_deg_out[s.y], 1.f));
    int p0 = atomicAdd(&g_cursor[d.x], 1);
    int p1 = atomicAdd(&g_cursor[d.y], 1);
    g_edge[p0] = make_int2(s.x, __float_as_int(w0));
    g_edge[p1] = make_int2(s.y, __float_as_int(w1));
}

// ---------------------------------------------------------------- agg inner: 8 edges/iter
__device__ __forceinline__ void agg_batch(const uint4* __restrict__ hp4, int2 rec,
                                          int cnt, int g, int c,
                                          float2& a0, float2& a1, float2& a2, float2& a3) {
    for (int j = 0; j < cnt; j += 8) {
        int sa  = __shfl_sync(0xffffffffu, rec.x, j + g);
        int wai = __shfl_sync(0xffffffffu, rec.y, j + g);
        int sb  = __shfl_sync(0xffffffffu, rec.x, j + 4 + g);
        int wbi = __shfl_sync(0xffffffffu, rec.y, j + 4 + g);
        uint4 va = hp4[(size_t)sa * 8 + c];
        uint4 vb = hp4[(size_t)sb * 8 + c];
        float wa = __int_as_float(wai);
        float wb = __int_as_float(wbi);
        const __half2* ha = (const __half2*)&va;
        const __half2* hb = (const __half2*)&vb;
        float2 f;
        f = __half22float2(ha[0]); a0.x += f.x * wa; a0.y += f.y * wa;
        f = __half22float2(ha[1]); a1.x += f.x * wa; a1.y += f.y * wa;
        f = __half22float2(ha[2]); a2.x += f.x * wa; a2.y += f.y * wa;
        f = __half22float2(ha[3]); a3.x += f.x * wa; a3.y += f.y * wa;
        f = __half22float2(hb[0]); a0.x += f.x * wb; a0.y += f.y * wb;
        f = __half22float2(hb[1]); a1.x += f.x * wb; a1.y += f.y * wb;
        f = __half22float2(hb[2]); a2.x += f.x * wb; a2.y += f.y * wb;
        f = __half22float2(hb[3]); a3.x += f.x * wb; a3.y += f.y * wb;
    }
}

// ---------------------------------------------------------------- fused layer
// 128 nodes/block, 256 threads, 8 warps. Warp w aggregates nodes [w*16, w*16+16)
// into fp16 Ash rows (stride 144B), then does its OWN m16n8k16 HMMA tile
// (M=16, N=64, K=64) with W staged fp16-transposed in SMEM. BN fused epilogue.
#define AST 72   // halves per Ash row (144 B)
template <bool OUT_HALF>
__global__ __launch_bounds__(256, 3) void k_layer(
    const __half* __restrict__ hin,
    const float* __restrict__ W,  const float* __restrict__ b,
    const float* __restrict__ gamma, const float* __restrict__ beta,
    const float* __restrict__ rm,    const float* __restrict__ rv,
    void* __restrict__ hout)
{
    __shared__ __half Ash[128 * AST];
    __shared__ __half Wt[64 * AST];
    __shared__ float s_scale[64], s_shift[64], s_bias[64];

    int t = threadIdx.x;
    int lane = t & 31;
    int w = t >> 5;
    int g = lane >> 3;
    int c = lane & 7;
    int nb = blockIdx.x * 128;

    // stage W fp32 [k][n] -> fp16 transposed Wt [n][k]
    for (int j4 = t; j4 < 1024; j4 += 256) {
        float4 v = ((const float4*)W)[j4];
        int lin = j4 * 4;
        int k = lin >> 6;
        int n = lin & 63;
        Wt[(n + 0) * AST + k] = __float2half(v.x);
        Wt[(n + 1) * AST + k] = __float2half(v.y);
        Wt[(n + 2) * AST + k] = __float2half(v.z);
        Wt[(n + 3) * AST + k] = __float2half(v.w);
    }
    if (t < 64) {
        float sc = rsqrtf(rv[t] + EPS) * gamma[t];
        s_scale[t] = sc;
        s_shift[t] = beta[t] - rm[t] * sc;
        s_bias[t]  = b[t];
    }
    __syncthreads();   // only block-wide barrier: Wt + BN constants visible

    // ---- aggregation: warp handles 16 nodes ----
    const uint4* hp4 = (const uint4*)hin;
    int nwbase = nb + w * 16;
    int ms = 0, md = 0;
    {
        int nn = nwbase + lane;
        if (lane < 16 && nn < N_NODES) { ms = g_start[nn]; md = g_deg_in[nn]; }
    }
    int e0n = __shfl_sync(0xffffffffu, ms, 0);
    int dgn = __shfl_sync(0xffffffffu, md, 0);
    int2 recn = make_int2(0, 0);
    if (lane < min(dgn, 32)) recn = g_edge[e0n + lane];

    #pragma unroll 1
    for (int i = 0; i < 16; i++) {
        int e0 = e0n, deg = dgn;
        int2 rec = recn;
        if (i < 15) {
            e0n = __shfl_sync(0xffffffffu, ms, i + 1);
            dgn = __shfl_sync(0xffffffffu, md, i + 1);
            recn = make_int2(0, 0);
            if (lane < min(dgn, 32)) recn = g_edge[e0n + lane];
        }
        float2 a0 = make_float2(0.f, 0.f), a1 = a0, a2 = a0, a3 = a0;
        agg_batch(hp4, rec, min(deg, 32), g, c, a0, a1, a2, a3);
        for (int e = e0 + 32; e < e0 + deg; e += 32) {
            int c2 = min(32, e0 + deg - e);
            int2 r2 = make_int2(0, 0);
            if (lane < c2) r2 = g_edge[e + lane];
            agg_batch(hp4, r2, c2, g, c, a0, a1, a2, a3);
        }
        #pragma unroll
        for (int m = 8; m <= 16; m <<= 1) {
            a0.x += __shfl_xor_sync(0xffffffffu, a0.x, m);
            a0.y += __shfl_xor_sync(0xffffffffu, a0.y, m);
            a1.x += __shfl_xor_sync(0xffffffffu, a1.x, m);
            a1.y += __shfl_xor_sync(0xffffffffu, a1.y, m);
            a2.x += __shfl_xor_sync(0xffffffffu, a2.x, m);
            a2.y += __shfl_xor_sync(0xffffffffu, a2.y, m);
            a3.x += __shfl_xor_sync(0xffffffffu, a3.x, m);
            a3.y += __shfl_xor_sync(0xffffffffu, a3.y, m);
        }
        if (g == 0) {
            float ri = rsqrtf(fmaxf((float)deg, 1.f));
            union { __half2 h2[4]; uint4 u; } pk;
            pk.h2[0] = __floats2half2_rn(a0.x * ri, a0.y * ri);
            pk.h2[1] = __floats2half2_rn(a1.x * ri, a1.y * ri);
            pk.h2[2] = __floats2half2_rn(a2.x * ri, a2.y * ri);
            pk.h2[3] = __floats2half2_rn(a3.x * ri, a3.y * ri);
            int row = w * 16 + i;
            *(uint4*)((char*)Ash + row * 144 + c * 16) = pk.u;
        }
    }
    __syncwarp();

    // ---- per-warp HMMA: M=16 (own rows) x N=64, K=64 ----
    float acc[8][4];
    #pragma unroll
    for (int nt = 0; nt < 8; nt++)
        #pragma unroll
        for (int j = 0; j < 4; j++) acc[nt][j] = 0.f;

    // ldmatrix lane addressing: rows (lane&15), k-halves (lane>>4)*8
    uint32_t a_base = smem_u32(Ash) + (w * 16 + (lane & 15)) * 144 + (lane >> 4) * 16;
    int bn = lane >> 2;          // B fragment n within tile
    int bks = (lane & 3) * 2;    // B fragment k pair

    #pragma unroll
    for (int ks = 0; ks < 4; ks++) {
        uint32_t a0, a1, a2, a3;
        asm volatile("ldmatrix.sync.aligned.m8n8.x4.shared.b16 {%0,%1,%2,%3}, [%4];"
            : "=r"(a0), "=r"(a1), "=r"(a2), "=r"(a3)
            : "r"(a_base + ks * 32));
        int kb = ks * 16;
        #pragma unroll
        for (int nt = 0; nt < 8; nt++) {
            uint32_t b0 = *(const uint32_t*)&Wt[(nt * 8 + bn) * AST + kb + bks];
            uint32_t b1 = *(const uint32_t*)&Wt[(nt * 8 + bn) * AST + kb + bks + 8];
            asm volatile(
                "mma.sync.aligned.m16n8k16.row.col.f32.f16.f16.f32 "
                "{%0,%1,%2,%3}, {%4,%5,%6,%7}, {%8,%9}, {%0,%1,%2,%3};"
                : "+f"(acc[nt][0]), "+f"(acc[nt][1]), "+f"(acc[nt][2]), "+f"(acc[nt][3])
                : "r"(a0), "r"(a1), "r"(a2), "r"(a3), "r"(b0), "r"(b1));
        }
    }

    // ---- epilogue: BN fused, direct stores ----
    int r0 = nb + w * 16 + (lane >> 2);
    int r1 = r0 + 8;
    #pragma unroll
    for (int nt = 0; nt < 8; nt++) {
        int col = nt * 8 + (lane & 3) * 2;
        float sc0 = s_scale[col],     sc1 = s_scale[col + 1];
        float sh0 = s_shift[col],     sh1 = s_shift[col + 1];
        float bb0 = s_bias[col],      bb1 = s_bias[col + 1];
        float y00 = fmaxf(fmaxf(acc[nt][0] + bb0, 0.f) * sc0 + sh0, 0.f);
        float y01 = fmaxf(fmaxf(acc[nt][1] + bb1, 0.f) * sc1 + sh1, 0.f);
        float y10 = fmaxf(fmaxf(acc[nt][2] + bb0, 0.f) * sc0 + sh0, 0.f);
        float y11 = fmaxf(fmaxf(acc[nt][3] + bb1, 0.f) * sc1 + sh1, 0.f);
        if (OUT_HALF) {
            __half* o = (__half*)hout;
            if (r0 < N_NODES) *(__half2*)&o[r0 * 64 + col] = __floats2half2_rn(y00, y01);
            if (r1 < N_NODES) *(__half2*)&o[r1 * 64 + col] = __floats2half2_rn(y10, y11);
        } else {
            float* o = (float*)hout;
            if (r0 < N_NODES) *(float2*)&o[r0 * 64 + col] = make_float2(y00, y01);
            if (r1 < N_NODES) *(float2*)&o[r1 * 64 + col] = make_float2(y10, y11);
        }
    }
}

// ---------------------------------------------------------------- readout
__global__ __launch_bounds__(256) void k_readout(const int* __restrict__ n2g,
                                                 float* __restrict__ out) {
    int g = blockIdx.x;
    __shared__ int slo, shi;
    if (threadIdx.x == 0) {
        int lo = 0, hi = N_NODES;
        while (lo < hi) { int m = (lo + hi) >> 1; if (n2g[m] < g) lo = m + 1; else hi = m; }
        slo = lo;
        hi = N_NODES;
        while (lo < hi) { int m = (lo + hi) >> 1; if (n2g[m] <= g) lo = m + 1; else hi = m; }
        shi = lo;
    }
    __syncthreads();
    int lo = slo, hi = shi;
    int d = threadIdx.x & 63;
    int rg = threadIdx.x >> 6;
    float acc = 0.f;
    for (int r = lo + rg; r < hi; r += 4)
        acc += g_h2[r * 64 + d];
    __shared__ float red[4][64];
    red[rg][d] = acc;
    __syncthreads();
    if (rg == 0) {
        float s = red[0][d] + red[1][d] + red[2][d] + red[3][d];
        out[g * 64 + d] = s / fmaxf((float)(hi - lo), 1.f);
    }
}

// ---------------------------------------------------------------- launch
extern "C" void kernel_launch(void* const* d_in, const int* in_sizes, int n_in,
                              void* d_out, int out_size) {
    const float* h   = (const float*)d_in[0];
    const float* ew  = (const float*)d_in[1];
    const int*   src = (const int*)d_in[2];
    const int*   dst = (const int*)d_in[3];
    const int*   n2g = (const int*)d_in[4];
    const float* W1 = (const float*)d_in[5];
    const float* b1 = (const float*)d_in[6];
    const float* gamma1 = (const float*)d_in[7];
    const float* beta1  = (const float*)d_in[8];
    const float* rm1 = (const float*)d_in[9];
    const float* rv1 = (const float*)d_in[10];
    const float* W2 = (const float*)d_in[11];
    const float* b2 = (const float*)d_in[12];
    const float* gamma2 = (const float*)d_in[13];
    const float* beta2  = (const float*)d_in[14];
    const float* rm2 = (const float*)d_in[15];
    const float* rv2 = (const float*)d_in[16];
    float* out = (float*)d_out;

    __half* hh0; cudaGetSymbolAddress((void**)&hh0, g_hh0);
    __half* hh1; cudaGetSymbolAddress((void**)&hh1, g_hh1);
    float*  h2;  cudaGetSymbolAddress((void**)&h2,  g_h2);

    const int TB = 256;
    int gN = (N_NODES + TB - 1) / TB;
    int gE2 = (N_EDGES / 2 + TB - 1) / TB;

    k_zero<<<gN, TB>>>();
    k_pre<<<GE4 + GH, TB>>>(src, dst, h);
    k_offsets<<<gN, TB>>>();
    k_bucket<<<gE2, TB>>>(src, dst, ew);

    int gL = (N_NODES + 127) / 128;
    k_layer<true ><<<gL, 256>>>(hh0, W1, b1, gamma1, beta1, rm1, rv1, hh1);
    k_layer<false><<<gL, 256>>>(hh1, W2, b2, gamma2, beta2, rm2, rv2, h2);

    k_readout<<<NGRAPH, 256>>>(n2g, out);
}

// round 12
// speedup vs baseline: 1.5929x; 1.0063x over previous
#include <cuda_runtime.h>
#include <cuda_fp16.h>
#include <cstdint>

#define N_NODES 100000
#define N_EDGES 1600000
#define D 64
#define NGRAPH 256
#define EPS 1e-5f

#define GE4 ((N_EDGES / 4 + 255) / 256)
#define GH  ((N_NODES * D / 8) / 256)

// ---- scratch ----
__device__ int    g_deg_out[N_NODES];
__device__ int    g_deg_in[N_NODES];
__device__ int    g_start[N_NODES];
__device__ int    g_cursor[N_NODES];
__device__ int    g_total;
__device__ int2   g_edge[N_EDGES];
__device__ __half g_hh0[N_NODES * D];
__device__ __half g_hh1[N_NODES * D];
__device__ float  g_h2[N_NODES * D];

__device__ __forceinline__ uint32_t smem_u32(const void* p) {
    uint32_t a;
    asm("{ .reg .u64 t; cvta.to.shared.u64 t, %1; cvt.u32.u64 %0, t; }"
        : "=r"(a) : "l"(p));
    return a;
}

// ---------------------------------------------------------------- zero
__global__ void k_zero() {
    int i = blockIdx.x * blockDim.x + threadIdx.x;
    if (i < N_NODES) { g_deg_out[i] = 0; g_deg_in[i] = 0; }
    if (i == 0) g_total = 0;
}

// ---------------------------------------------------------------- fat pre
__global__ void k_pre(const int* __restrict__ src, const int* __restrict__ dst,
                      const float* __restrict__ h) {
    int b = blockIdx.x;
    if (b < GE4) {
        int e4 = b * 256 + threadIdx.x;
        if (e4 * 4 >= N_EDGES) return;
        int4 s = ((const int4*)src)[e4];
        int4 d = ((const int4*)dst)[e4];
        atomicAdd(&g_deg_out[s.x], 1); atomicAdd(&g_deg_out[s.y], 1);
        atomicAdd(&g_deg_out[s.z], 1); atomicAdd(&g_deg_out[s.w], 1);
        atomicAdd(&g_deg_in[d.x], 1);  atomicAdd(&g_deg_in[d.y], 1);
        atomicAdd(&g_deg_in[d.z], 1);  atomicAdd(&g_deg_in[d.w], 1);
    } else {
        int i = (b - GE4) * 256 + threadIdx.x;
        float4 a = ((const float4*)h)[i * 2];
        float4 c = ((const float4*)h)[i * 2 + 1];
        union { __half2 h2[4]; uint4 u; } pk;
        pk.h2[0] = __floats2half2_rn(a.x, a.y);
        pk.h2[1] = __floats2half2_rn(a.z, a.w);
        pk.h2[2] = __floats2half2_rn(c.x, c.y);
        pk.h2[3] = __floats2half2_rn(c.z, c.w);
        ((uint4*)g_hh0)[i] = pk.u;
    }
}

// ---------------------------------------------------------------- offsets
__global__ void k_offsets() {
    int i = blockIdx.x * 256 + threadIdx.x;
    int d = (i < N_NODES) ? g_deg_in[i] : 0;
    int lane = threadIdx.x & 31, wid = threadIdx.x >> 5;
    int s = d;
    #pragma unroll
    for (int o = 1; o < 32; o <<= 1) {
        int x = __shfl_up_sync(0xffffffffu, s, o);
        if (lane >= o) s += x;
    }
    __shared__ int woff[8];
    __shared__ int sbase;
    if (lane == 31) woff[wid] = s;
    __syncthreads();
    if (threadIdx.x < 8) {
        int w = woff[threadIdx.x];
        int t = w;
        #pragma unroll
        for (int o = 1; o < 8; o <<= 1) {
            int x = __shfl_up_sync(0xffu, t, o);
            if ((int)threadIdx.x >= o) t += x;
        }
        woff[threadIdx.x] = t - w;
        if (threadIdx.x == 7) sbase = atomicAdd(&g_total, t);
    }
    __syncthreads();
    if (i < N_NODES) {
        int start = sbase + woff[wid] + (s - d);
        g_start[i] = start;
        g_cursor[i] = start;
    }
}

// ---------------------------------------------------------------- bucket
__global__ void k_bucket(const int* __restrict__ src, const int* __restrict__ dst,
                         const float* __restrict__ ew) {
    int e2 = (blockIdx.x * blockDim.x + threadIdx.x) * 2;
    if (e2 >= N_EDGES) return;
    int2 s = *(const int2*)(src + e2);
    int2 d = *(const int2*)(dst + e2);
    float2 w = *(const float2*)(ew + e2);
    float w0 = w.x * rsqrtf(fmaxf((float)g_deg_out[s.x], 1.f));
    float w1 = w.y * rsqrtf(fmaxf((float)g_deg_out[s.y], 1.f));
    int p0 = atomicAdd(&g_cursor[d.x], 1);
    int p1 = atomicAdd(&g_cursor[d.y], 1);
    g_edge[p0] = make_int2(s.x, __float_as_int(w0));
    g_edge[p1] = make_int2(s.y, __float_as_int(w1));
}

// ---------------------------------------------------------------- agg inner: 8 edges/iter
__device__ __forceinline__ void agg_batch(const uint4* __restrict__ hp4, int2 rec,
                                          int cnt, int g, int c,
                                          float2& a0, float2& a1, float2& a2, float2& a3) {
    for (int j = 0; j < cnt; j += 8) {
        int sa  = __shfl_sync(0xffffffffu, rec.x, j + g);
        int wai = __shfl_sync(0xffffffffu, rec.y, j + g);
        int sb  = __shfl_sync(0xffffffffu, rec.x, j + 4 + g);
        int wbi = __shfl_sync(0xffffffffu, rec.y, j + 4 + g);
        uint4 va = hp4[(size_t)sa * 8 + c];
        uint4 vb = hp4[(size_t)sb * 8 + c];
        float wa = __int_as_float(wai);
        float wb = __int_as_float(wbi);
        const __half2* ha = (const __half2*)&va;
        const __half2* hb = (const __half2*)&vb;
        float2 f;
        f = __half22float2(ha[0]); a0.x += f.x * wa; a0.y += f.y * wa;
        f = __half22float2(ha[1]); a1.x += f.x * wa; a1.y += f.y * wa;
        f = __half22float2(ha[2]); a2.x += f.x * wa; a2.y += f.y * wa;
        f = __half22float2(ha[3]); a3.x += f.x * wa; a3.y += f.y * wa;
        f = __half22float2(hb[0]); a0.x += f.x * wb; a0.y += f.y * wb;
        f = __half22float2(hb[1]); a1.x += f.x * wb; a1.y += f.y * wb;
        f = __half22float2(hb[2]); a2.x += f.x * wb; a2.y += f.y * wb;
        f = __half22float2(hb[3]); a3.x += f.x * wb; a3.y += f.y * wb;
    }
}

// ---------------------------------------------------------------- fused layer
// 128 nodes/block, 256 threads, 8 warps. Warp w aggregates nodes [w*16, w*16+16)
// into fp16 Ash rows (stride 144B), then does its OWN m16n8k16 HMMA tile
// (M=16, N=64, K=64) with W staged fp16-transposed in SMEM. BN fused epilogue.
#define AST 72   // halves per Ash row (144 B)
template <bool OUT_HALF>
__global__ __launch_bounds__(256, 3) void k_layer(
    const __half* __restrict__ hin,
    const float* __restrict__ W,  const float* __restrict__ b,
    const float* __restrict__ gamma, const float* __restrict__ beta,
    const float* __restrict__ rm,    const float* __restrict__ rv,
    void* __restrict__ hout)
{
    __shared__ __half Ash[128 * AST];
    __shared__ __half Wt[64 * AST];
    __shared__ float s_scale[64], s_shift[64], s_bias[64];

    int t = threadIdx.x;
    int lane = t & 31;
    int w = t >> 5;
    int g = lane >> 3;
    int c = lane & 7;
    int nb = blockIdx.x * 128;

    // stage W fp32 [k][n] -> fp16 transposed Wt [n][k]
    for (int j4 = t; j4 < 1024; j4 += 256) {
        float4 v = ((const float4*)W)[j4];
        int lin = j4 * 4;
        int k = lin >> 6;
        int n = lin & 63;
        Wt[(n + 0) * AST + k] = __float2half(v.x);
        Wt[(n + 1) * AST + k] = __float2half(v.y);
        Wt[(n + 2) * AST + k] = __float2half(v.z);
        Wt[(n + 3) * AST + k] = __float2half(v.w);
    }
    if (t < 64) {
        float sc = rsqrtf(rv[t] + EPS) * gamma[t];
        s_scale[t] = sc;
        s_shift[t] = beta[t] - rm[t] * sc;
        s_bias[t]  = b[t];
    }
    __syncthreads();   // only block-wide barrier: Wt + BN constants visible

    // ---- aggregation: warp handles 16 nodes ----
    const uint4* hp4 = (const uint4*)hin;
    int nwbase = nb + w * 16;
    int ms = 0, md = 0;
    {
        int nn = nwbase + lane;
        if (lane < 16 && nn < N_NODES) { ms = g_start[nn]; md = g_deg_in[nn]; }
    }
    int e0n = __shfl_sync(0xffffffffu, ms, 0);
    int dgn = __shfl_sync(0xffffffffu, md, 0);
    int2 recn = make_int2(0, 0);
    if (lane < min(dgn, 32)) recn = g_edge[e0n + lane];

    #pragma unroll 1
    for (int i = 0; i < 16; i++) {
        int e0 = e0n, deg = dgn;
        int2 rec = recn;
        if (i < 15) {
            e0n = __shfl_sync(0xffffffffu, ms, i + 1);
            dgn = __shfl_sync(0xffffffffu, md, i + 1);
            recn = make_int2(0, 0);
            if (lane < min(dgn, 32)) recn = g_edge[e0n + lane];
        }
        float2 a0 = make_float2(0.f, 0.f), a1 = a0, a2 = a0, a3 = a0;
        agg_batch(hp4, rec, min(deg, 32), g, c, a0, a1, a2, a3);
        for (int e = e0 + 32; e < e0 + deg; e += 32) {
            int c2 = min(32, e0 + deg - e);
            int2 r2 = make_int2(0, 0);
            if (lane < c2) r2 = g_edge[e + lane];
            agg_batch(hp4, r2, c2, g, c, a0, a1, a2, a3);
        }
        #pragma unroll
        for (int m = 8; m <= 16; m <<= 1) {
            a0.x += __shfl_xor_sync(0xffffffffu, a0.x, m);
            a0.y += __shfl_xor_sync(0xffffffffu, a0.y, m);
            a1.x += __shfl_xor_sync(0xffffffffu, a1.x, m);
            a1.y += __shfl_xor_sync(0xffffffffu, a1.y, m);
            a2.x += __shfl_xor_sync(0xffffffffu, a2.x, m);
            a2.y += __shfl_xor_sync(0xffffffffu, a2.y, m);
            a3.x += __shfl_xor_sync(0xffffffffu, a3.x, m);
            a3.y += __shfl_xor_sync(0xffffffffu, a3.y, m);
        }
        if (g == 0) {
            float ri = rsqrtf(fmaxf((float)deg, 1.f));
            union { __half2 h2[4]; uint4 u; } pk;
            pk.h2[0] = __floats2half2_rn(a0.x * ri, a0.y * ri);
            pk.h2[1] = __floats2half2_rn(a1.x * ri, a1.y * ri);
            pk.h2[2] = __floats2half2_rn(a2.x * ri, a2.y * ri);
            pk.h2[3] = __floats2half2_rn(a3.x * ri, a3.y * ri);
            int row = w * 16 + i;
            *(uint4*)((char*)Ash + row * 144 + c * 16) = pk.u;
        }
    }
    __syncwarp();

    // ---- per-warp HMMA: M=16 (own rows) x N=64, K=64 ----
    float acc[8][4];
    #pragma unroll
    for (int nt = 0; nt < 8; nt++)
        #pragma unroll
        for (int j = 0; j < 4; j++) acc[nt][j] = 0.f;

    // ldmatrix lane addressing: rows (lane&15), k-halves (lane>>4)*8
    uint32_t a_base = smem_u32(Ash) + (w * 16 + (lane & 15)) * 144 + (lane >> 4) * 16;
    int bn = lane >> 2;          // B fragment n within tile
    int bks = (lane & 3) * 2;    // B fragment k pair

    #pragma unroll
    for (int ks = 0; ks < 4; ks++) {
        uint32_t a0, a1, a2, a3;
        asm volatile("ldmatrix.sync.aligned.m8n8.x4.shared.b16 {%0,%1,%2,%3}, [%4];"
            : "=r"(a0), "=r"(a1), "=r"(a2), "=r"(a3)
            : "r"(a_base + ks * 32));
        int kb = ks * 16;
        #pragma unroll
        for (int nt = 0; nt < 8; nt++) {
            uint32_t b0 = *(const uint32_t*)&Wt[(nt * 8 + bn) * AST + kb + bks];
            uint32_t b1 = *(const uint32_t*)&Wt[(nt * 8 + bn) * AST + kb + bks + 8];
            asm volatile(
                "mma.sync.aligned.m16n8k16.row.col.f32.f16.f16.f32 "
                "{%0,%1,%2,%3}, {%4,%5,%6,%7}, {%8,%9}, {%0,%1,%2,%3};"
                : "+f"(acc[nt][0]), "+f"(acc[nt][1]), "+f"(acc[nt][2]), "+f"(acc[nt][3])
                : "r"(a0), "r"(a1), "r"(a2), "r"(a3), "r"(b0), "r"(b1));
        }
    }

    // ---- epilogue: BN fused, direct stores ----
    int r0 = nb + w * 16 + (lane >> 2);
    int r1 = r0 + 8;
    #pragma unroll
    for (int nt = 0; nt < 8; nt++) {
        int col = nt * 8 + (lane & 3) * 2;
        float sc0 = s_scale[col],     sc1 = s_scale[col + 1];
        float sh0 = s_shift[col],     sh1 = s_shift[col + 1];
        float bb0 = s_bias[col],      bb1 = s_bias[col + 1];
        float y00 = fmaxf(fmaxf(acc[nt][0] + bb0, 0.f) * sc0 + sh0, 0.f);
        float y01 = fmaxf(fmaxf(acc[nt][1] + bb1, 0.f) * sc1 + sh1, 0.f);
        float y10 = fmaxf(fmaxf(acc[nt][2] + bb0, 0.f) * sc0 + sh0, 0.f);
        float y11 = fmaxf(fmaxf(acc[nt][3] + bb1, 0.f) * sc1 + sh1, 0.f);
        if (OUT_HALF) {
            __half* o = (__half*)hout;
            if (r0 < N_NODES) *(__half2*)&o[r0 * 64 + col] = __floats2half2_rn(y00, y01);
            if (r1 < N_NODES) *(__half2*)&o[r1 * 64 + col] = __floats2half2_rn(y10, y11);
        } else {
            float* o = (float*)hout;
            if (r0 < N_NODES) *(float2*)&o[r0 * 64 + col] = make_float2(y00, y01);
            if (r1 < N_NODES) *(float2*)&o[r1 * 64 + col] = make_float2(y10, y11);
        }
    }
}

// ---------------------------------------------------------------- readout
__global__ __launch_bounds__(256) void k_readout(const int* __restrict__ n2g,
                                                 float* __restrict__ out) {
    int g = blockIdx.x;
    __shared__ int slo, shi;
    if (threadIdx.x == 0) {
        int lo = 0, hi = N_NODES;
        while (lo < hi) { int m = (lo + hi) >> 1; if (n2g[m] < g) lo = m + 1; else hi = m; }
        slo = lo;
        hi = N_NODES;
        while (lo < hi) { int m = (lo + hi) >> 1; if (n2g[m] <= g) lo = m + 1; else hi = m; }
        shi = lo;
    }
    __syncthreads();
    int lo = slo, hi = shi;
    int d = threadIdx.x & 63;
    int rg = threadIdx.x >> 6;
    float acc = 0.f;
    for (int r = lo + rg; r < hi; r += 4)
        acc += g_h2[r * 64 + d];
    __shared__ float red[4][64];
    red[rg][d] = acc;
    __syncthreads();
    if (rg == 0) {
        float s = red[0][d] + red[1][d] + red[2][d] + red[3][d];
        out[g * 64 + d] = s / fmaxf((float)(hi - lo), 1.f);
    }
}

// ---------------------------------------------------------------- launch
extern "C" void kernel_launch(void* const* d_in, const int* in_sizes, int n_in,
                              void* d_out, int out_size) {
    const float* h   = (const float*)d_in[0];
    const float* ew  = (const float*)d_in[1];
    const int*   src = (const int*)d_in[2];
    const int*   dst = (const int*)d_in[3];
    const int*   n2g = (const int*)d_in[4];
    const float* W1 = (const float*)d_in[5];
    const float* b1 = (const float*)d_in[6];
    const float* gamma1 = (const float*)d_in[7];
    const float* beta1  = (const float*)d_in[8];
    const float* rm1 = (const float*)d_in[9];
    const float* rv1 = (const float*)d_in[10];
    const float* W2 = (const float*)d_in[11];
    const float* b2 = (const float*)d_in[12];
    const float* gamma2 = (const float*)d_in[13];
    const float* beta2  = (const float*)d_in[14];
    const float* rm2 = (const float*)d_in[15];
    const float* rv2 = (const float*)d_in[16];
    float* out = (float*)d_out;

    __half* hh0; cudaGetSymbolAddress((void**)&hh0, g_hh0);
    __half* hh1; cudaGetSymbolAddress((void**)&hh1, g_hh1);
    float*  h2;  cudaGetSymbolAddress((void**)&h2,  g_h2);

    const int TB = 256;
    int gN = (N_NODES + TB - 1) / TB;
    int gE2 = (N_EDGES / 2 + TB - 1) / TB;

    k_zero<<<gN, TB>>>();
    k_pre<<<GE4 + GH, TB>>>(src, dst, h);
    k_offsets<<<gN, TB>>>();
    k_bucket<<<gE2, TB>>>(src, dst, ew);

    int gL = (N_NODES + 127) / 128;
    k_layer<true ><<<gL, 256>>>(hh0, W1, b1, gamma1, beta1, rm1, rv1, hh1);
    k_layer<false><<<gL, 256>>>(hh1, W2, b2, gamma2, beta2, rm2, rv2, h2);

    k_readout<<<NGRAPH, 256>>>(n2g, out);
}